// round 15
// baseline (speedup 1.0000x reference)
#include <cuda_runtime.h>
#include <cuda_bf16.h>
#include <math.h>
#include <stdint.h>

#define NN 100000
#define NP 100096
#define EE 600000
#define DD 128
#define SS 3
#define GG 64
#define OUTD 2
#define NPS (SS * NP)
#define M_TILES (NP / 128)        // 782

// ---------------- device scratch ----------------
__device__ __nv_bfloat16 g_xb[NP * DD];
__device__ __nv_bfloat16 g_hb3[SS * NP * DD];
__device__ __nv_bfloat16 g_agg3[SS * NP * DD];
__device__ __nv_bfloat16 g_gh3[SS * NP * 3 * DD];
__device__ __nv_bfloat16 g_wcb[SS * 3 * DD * DD];     // block-interleaved combined, i=0
__device__ __nv_bfloat16 g_wcb2[SS * 3 * DD * DD];    // i=1
__device__ __nv_bfloat16 g_wihb[SS * 3 * DD * DD];    // block-interleaved rows
__device__ __nv_bfloat16 g_whhb[SS * 3 * DD * DD];
__device__ __nv_bfloat16 g_Wb[SS * 2 * DD * DD];
__device__ float g_bihr[SS * 3 * DD];                 // block-interleaved bias
__device__ float g_pool[GG * DD];
__device__ float g_cnt[GG];
__device__ int   g_bsrc[EE];
__device__ int   g_ecnt[NPS];
__device__ int   g_ecur[NPS];
__device__ int   g_eoff[NPS + 1];

// ---------------- tiny utils ----------------
__global__ void zero_kernel(float* __restrict__ p, int n4) {
    int i = blockIdx.x * blockDim.x + threadIdx.x;
    if (i < n4) ((float4*)p)[i] = make_float4(0.f, 0.f, 0.f, 0.f);
}
__global__ void copy_pad_kernel(const float* __restrict__ x, __nv_bfloat16* __restrict__ xb) {
    int i = blockIdx.x * blockDim.x + threadIdx.x;
    if (i >= NP * 32) return;
    int n = i >> 5;
    float4 v = make_float4(0.f, 0.f, 0.f, 0.f);
    if (n < NN) v = ((const float4*)x)[i];
    *(__nv_bfloat162*)(xb + (size_t)i * 4)     = __floats2bfloat162_rn(v.x, v.y);
    *(__nv_bfloat162*)(xb + (size_t)i * 4 + 2) = __floats2bfloat162_rn(v.z, v.w);
}
__global__ void cvt_bf16_kernel(const float* __restrict__ src,
                                __nv_bfloat16* __restrict__ dst, int n4) {
    int i = blockIdx.x * blockDim.x + threadIdx.x;
    if (i >= n4) return;
    float4 v = ((const float4*)src)[i];
    *(__nv_bfloat162*)(dst + (size_t)i * 4)     = __floats2bfloat162_rn(v.x, v.y);
    *(__nv_bfloat162*)(dst + (size_t)i * 4 + 2) = __floats2bfloat162_rn(v.z, v.w);
}
// wih rows: j = g*128+d  ->  jil = (d/8)*24 + g*8 + (d%8)   (per s), fp32 -> bf16
__global__ void cvt_wih_il_kernel(const float* __restrict__ wih,
                                  __nv_bfloat16* __restrict__ dst) {
    int i = blockIdx.x * blockDim.x + threadIdx.x;      // SS*384*32 float4 units
    if (i >= SS * 384 * 32) return;
    int s = i / (384 * 32);
    int rem = i - s * 384 * 32;
    int j = rem >> 5;
    int k4 = (rem & 31) * 4;
    int g = j >> 7;
    int d = j & 127;
    int jil = (d >> 3) * 24 + g * 8 + (d & 7);
    float4 v = *(const float4*)(wih + (size_t)(s * 384 + j) * 128 + k4);
    __nv_bfloat16* o = dst + (size_t)(s * 384 + jil) * 128 + k4;
    *(__nv_bfloat162*)(o)     = __floats2bfloat162_rn(v.x, v.y);
    *(__nv_bfloat162*)(o + 2) = __floats2bfloat162_rn(v.z, v.w);
}
__global__ void bihr_kernel(const float* __restrict__ bih, float* __restrict__ bihr) {
    int i = blockIdx.x * blockDim.x + threadIdx.x;
    if (i >= SS * 384) return;
    int s = i / 384;
    int j = i - s * 384;
    int g = j >> 7;
    int d = j & 127;
    int jil = (d >> 3) * 24 + g * 8 + (d & 7);
    bihr[s * 384 + jil] = bih[i];
}
__global__ void zero2_ints(int* __restrict__ a, int* __restrict__ b, int n) {
    int i = blockIdx.x * blockDim.x + threadIdx.x;
    if (i < n) { a[i] = 0; b[i] = 0; }
}

// ---------------- CSR build ----------------
__global__ void ecount_kernel(const int* __restrict__ dst, const int* __restrict__ attr,
                              int* __restrict__ cnt, int E) {
    int e = blockIdx.x * blockDim.x + threadIdx.x;
    if (e < E) atomicAdd(&cnt[attr[e] * NP + dst[e]], 1);
}
__global__ void scan_kernel(const int* __restrict__ cnt, int* __restrict__ off, int n) {
    __shared__ int ssum[1024];
    int t = threadIdx.x;
    int per = (n + 1023) / 1024;
    int b0 = t * per;
    int b1 = b0 + per; if (b1 > n) b1 = n; if (b0 > n) b0 = n;
    int s = 0;
    for (int i = b0; i < b1; i++) s += cnt[i];
    ssum[t] = s;
    __syncthreads();
    for (int d = 1; d < 1024; d <<= 1) {
        int v = (t >= d) ? ssum[t - d] : 0;
        __syncthreads();
        ssum[t] += v;
        __syncthreads();
    }
    int run = (t == 0) ? 0 : ssum[t - 1];
    if (t == 1023) off[n] = ssum[1023];
    for (int i = b0; i < b1; i++) { off[i] = run; run += cnt[i]; }
}
__global__ void fill_kernel(const int* __restrict__ src, const int* __restrict__ dst,
                            const int* __restrict__ attr, const int* __restrict__ off,
                            int* __restrict__ cur, int* __restrict__ bsrc, int E) {
    int e = blockIdx.x * blockDim.x + threadIdx.x;
    if (e >= E) return;
    int idx = attr[e] * NP + dst[e];
    int pos = off[idx] + atomicAdd(&cur[idx], 1);
    bsrc[pos] = src[e];
}

// ---------------- gather all 3 types ----------------
struct Feat3 { const __nv_bfloat16* p[3]; };

__global__ void gather3_kernel(const int* __restrict__ off, const int* __restrict__ bsrc,
                               Feat3 f, __nv_bfloat16* __restrict__ agg3) {
    int w = (blockIdx.x * blockDim.x + threadIdx.x) >> 5;
    int lane = threadIdx.x & 31;
    if (w >= SS * NP) return;
    int s = w / NP;
    const __nv_bfloat16* feat = f.p[s];
    int e0 = off[w], e1 = off[w + 1];
    float a0 = 0.f, a1 = 0.f, a2 = 0.f, a3 = 0.f;
    for (int e = e0; e < e1; e++) {
        int sn = bsrc[e];
        uint2 u = *(const uint2*)(feat + (size_t)sn * DD + lane * 4);
        __nv_bfloat162 p0 = *(__nv_bfloat162*)&u.x;
        __nv_bfloat162 p1 = *(__nv_bfloat162*)&u.y;
        float2 f0 = __bfloat1622float2(p0), f1 = __bfloat1622float2(p1);
        a0 += f0.x; a1 += f0.y; a2 += f1.x; a3 += f1.y;
    }
    if (e1 > e0) {
        float inv = 1.0f / (float)(e1 - e0);
        a0 *= inv; a1 *= inv; a2 *= inv; a3 *= inv;
    }
    uint2 o;
    *(__nv_bfloat162*)&o.x = __floats2bfloat162_rn(a0, a1);
    *(__nv_bfloat162*)&o.y = __floats2bfloat162_rn(a2, a3);
    *(uint2*)(agg3 + (size_t)w * DD + lane * 4) = o;
}

// ---------------- mma helpers ----------------
#define LDTB 136
__device__ __forceinline__ void cp16(void* s, const void* g) {
    uint32_t sa = (uint32_t)__cvta_generic_to_shared(s);
    asm volatile("cp.async.cg.shared.global [%0], [%1], 16;" :: "r"(sa), "l"(g));
}
__device__ __forceinline__ void ldm_x4(uint32_t* r, const __nv_bfloat16* p) {
    uint32_t sa = (uint32_t)__cvta_generic_to_shared(p);
    asm volatile("ldmatrix.sync.aligned.m8n8.x4.shared.b16 {%0,%1,%2,%3}, [%4];"
                 : "=r"(r[0]), "=r"(r[1]), "=r"(r[2]), "=r"(r[3]) : "r"(sa));
}
__device__ __forceinline__ void ldm_x2(uint32_t* r, const __nv_bfloat16* p) {
    uint32_t sa = (uint32_t)__cvta_generic_to_shared(p);
    asm volatile("ldmatrix.sync.aligned.m8n8.x2.shared.b16 {%0,%1}, [%2];"
                 : "=r"(r[0]), "=r"(r[1]) : "r"(sa));
}
__device__ __forceinline__ void mma16816(float* c, const uint32_t* a, const uint32_t* b) {
    asm volatile(
        "mma.sync.aligned.m16n8k16.row.col.f32.bf16.bf16.f32 "
        "{%0,%1,%2,%3}, {%4,%5,%6,%7}, {%8,%9}, {%0,%1,%2,%3};"
        : "+f"(c[0]), "+f"(c[1]), "+f"(c[2]), "+f"(c[3])
        : "r"(a[0]), "r"(a[1]), "r"(a[2]), "r"(a[3]), "r"(b[0]), "r"(b[1]));
}
__device__ __forceinline__ float tanhapx(float x) {
    float y;
    asm("tanh.approx.f32 %0, %1;" : "=f"(y) : "f"(x));
    return y;
}
__device__ __forceinline__ float sigf(float x) {
    return 0.5f * tanhapx(0.5f * x) + 0.5f;
}
__device__ __forceinline__ float4 ldbf4(const __nv_bfloat16* p) {
    uint2 u = *(const uint2*)p;
    __nv_bfloat162 a = *(__nv_bfloat162*)&u.x;
    __nv_bfloat162 b = *(__nv_bfloat162*)&u.y;
    float2 fa = __bfloat1622float2(a), fb = __bfloat1622float2(b);
    return make_float4(fa.x, fa.y, fb.x, fb.y);
}
__device__ __forceinline__ float2 ldbf2(const __nv_bfloat16* p) {
    uint32_t u = *(const uint32_t*)p;
    return __bfloat1622float2(*(__nv_bfloat162*)&u);
}
__device__ __forceinline__ void stbf4(__nv_bfloat16* p, float4 v) {
    uint2 u;
    *(__nv_bfloat162*)&u.x = __floats2bfloat162_rn(v.x, v.y);
    *(__nv_bfloat162*)&u.y = __floats2bfloat162_rn(v.z, v.w);
    *(uint2*)p = u;
}

// ========== plain weights-stationary GEMM (gh + wc), R12 core ==========
#define SMB_B (128 * LDTB * 2)
#define SMB_A (128 * LDTB * 2)
#define BG_SMEM (SMB_B + 2 * SMB_A)  // 104448
#define GEMM_T 512

struct GemmArgs {
    const __nv_bfloat16* A[6];
    const __nv_bfloat16* B[6];
    const float* bias[6];
    __nv_bfloat16* C[6];
};

__global__ void __launch_bounds__(GEMM_T, 1)
bf16_gemm(GemmArgs ga, int J, int mtiles) {
    int z = blockIdx.z;
    const __nv_bfloat16* A = ga.A[z];
    const __nv_bfloat16* B = ga.B[z];
    const float* bias = ga.bias[z];
    __nv_bfloat16* C = ga.C[z];

    extern __shared__ char smx[];
    __nv_bfloat16* Bs = (__nv_bfloat16*)smx;
    __nv_bfloat16* Abuf0 = (__nv_bfloat16*)(smx + SMB_B);
    __nv_bfloat16* Abuf1 = (__nv_bfloat16*)(smx + SMB_B + SMB_A);

    int tid = threadIdx.x;
    int warp = tid >> 5;
    int lane = tid & 31;
    int mb = (warp >> 2) * 32;
    int nb = (warp & 3) * 32;
    int bn = blockIdx.x * 128;

    int mt = blockIdx.y;
    if (mt >= mtiles) return;

    for (int slot = tid; slot < 128 * 16; slot += GEMM_T) {
        int r = slot >> 4;
        int c8 = (slot & 15) * 8;
        cp16(Bs + r * LDTB + c8, B + (size_t)(bn + r) * 128 + c8);
    }
    asm volatile("cp.async.commit_group;");
    for (int slot = tid; slot < 128 * 16; slot += GEMM_T) {
        int r = slot >> 4;
        int c8 = (slot & 15) * 8;
        cp16(Abuf0 + r * LDTB + c8, A + (size_t)mt * 128 * 128 + (size_t)r * 128 + c8);
    }
    asm volatile("cp.async.commit_group;");
    asm volatile("cp.async.wait_group 1;");
    __syncthreads();

    uint32_t bf[4][8][2];
    {
        int lr = lane & 7;
        int ls = (lane >> 3) & 1;
#pragma unroll
        for (int nt = 0; nt < 4; nt++)
#pragma unroll
            for (int kt = 0; kt < 8; kt++)
                ldm_x2(bf[nt][kt], Bs + (nb + nt * 8 + lr) * LDTB + kt * 16 + ls * 8);
    }

    int buf = 0;
    while (mt < mtiles) {
        int nxt = mt + gridDim.y;
        bool pf = (nxt < mtiles);
        __nv_bfloat16* Acur = buf ? Abuf1 : Abuf0;
        __nv_bfloat16* Aalt = buf ? Abuf0 : Abuf1;
        if (pf) {
            for (int slot = tid; slot < 128 * 16; slot += GEMM_T) {
                int r = slot >> 4;
                int c8 = (slot & 15) * 8;
                cp16(Aalt + r * LDTB + c8,
                     A + (size_t)nxt * 128 * 128 + (size_t)r * 128 + c8);
            }
            asm volatile("cp.async.commit_group;");
            asm volatile("cp.async.wait_group 1;");
        } else {
            asm volatile("cp.async.wait_group 0;");
        }
        __syncthreads();

        float acc[2][4][4];
#pragma unroll
        for (int i = 0; i < 2; i++)
#pragma unroll
            for (int nt = 0; nt < 4; nt++)
#pragma unroll
                for (int e = 0; e < 4; e++) acc[i][nt][e] = 0.f;

        int q = lane >> 3;
        int arow = (q & 1) * 8 + (lane & 7);
        int acol = (q >> 1) * 8;
#pragma unroll
        for (int kt = 0; kt < 8; kt++) {
            uint32_t a[2][4];
#pragma unroll
            for (int i = 0; i < 2; i++)
                ldm_x4(a[i], Acur + (mb + i * 16 + arow) * LDTB + kt * 16 + acol);
#pragma unroll
            for (int i = 0; i < 2; i++)
#pragma unroll
                for (int nt = 0; nt < 4; nt++)
                    mma16816(acc[i][nt], a[i], bf[nt][kt]);
        }

        int bm = mt * 128;
#pragma unroll
        for (int i = 0; i < 2; i++) {
#pragma unroll
            for (int nt = 0; nt < 4; nt++) {
                int r0 = bm + mb + i * 16 + (lane >> 2);
                int cc = bn + nb + nt * 8 + ((lane & 3) << 1);
                float b0v = 0.f, b1v = 0.f;
                if (bias != nullptr) { b0v = bias[cc]; b1v = bias[cc + 1]; }
                *(__nv_bfloat162*)(C + (size_t)r0 * J + cc) =
                    __floats2bfloat162_rn(acc[i][nt][0] + b0v, acc[i][nt][1] + b1v);
                *(__nv_bfloat162*)(C + (size_t)(r0 + 8) * J + cc) =
                    __floats2bfloat162_rn(acc[i][nt][2] + b0v, acc[i][nt][3] + b1v);
            }
        }
        __syncthreads();
        mt = nxt;
        buf ^= 1;
    }
}

// ========== fused gi-GEMM + register GRU epilogue (block-interleaved Wc) ==========
// Stripe = 96 cols = 4 dim-blocks x (3 gates x 8 dims). Warp tile 32(M) x 24(N):
// one dim-block, n8 tile nt == gate nt. GRU runs on fp32 accumulators directly.
#define SMB_B2 (96 * LDTB * 2)           // 26112
#define FG_SMEM (SMB_B2 + 2 * SMB_A)     // 95744

struct FusedArgs {
    const __nv_bfloat16* A[3];
    const __nv_bfloat16* B[3];
    const __nv_bfloat16* gh[3];
    const __nv_bfloat16* hold[3];
    __nv_bfloat16* out[3];
    const float* bias[3];
};

__global__ void __launch_bounds__(GEMM_T, 1)
gemm_gru(FusedArgs fa, int mtiles) {
    int s = blockIdx.z;
    const __nv_bfloat16* A = fa.A[s];
    const __nv_bfloat16* B = fa.B[s];
    const __nv_bfloat16* gh = fa.gh[s];
    const __nv_bfloat16* hold = fa.hold[s];
    __nv_bfloat16* outp = fa.out[s];
    const float* bias = fa.bias[s];

    extern __shared__ char smx[];
    __nv_bfloat16* Bs = (__nv_bfloat16*)smx;
    __nv_bfloat16* Abuf0 = (__nv_bfloat16*)(smx + SMB_B2);
    __nv_bfloat16* Abuf1 = (__nv_bfloat16*)(smx + SMB_B2 + SMB_A);

    int tid = threadIdx.x;
    int warp = tid >> 5;
    int lane = tid & 31;
    int mb = (warp >> 2) * 32;
    int nb = (warp & 3) * 24;      // dim-block (warp&3)
    int bnr = blockIdx.x * 96;
    int D0 = blockIdx.x * 32;

    int mt = blockIdx.y;
    if (mt >= mtiles) return;

    for (int slot = tid; slot < 96 * 16; slot += GEMM_T) {
        int r = slot >> 4;
        int c8 = (slot & 15) * 8;
        cp16(Bs + r * LDTB + c8, B + (size_t)(bnr + r) * 128 + c8);
    }
    asm volatile("cp.async.commit_group;");
    for (int slot = tid; slot < 128 * 16; slot += GEMM_T) {
        int r = slot >> 4;
        int c8 = (slot & 15) * 8;
        cp16(Abuf0 + r * LDTB + c8, A + (size_t)mt * 128 * 128 + (size_t)r * 128 + c8);
    }
    asm volatile("cp.async.commit_group;");
    asm volatile("cp.async.wait_group 1;");
    __syncthreads();

    uint32_t bfr[3][8][2];
    {
        int lr = lane & 7;
        int ls = (lane >> 3) & 1;
#pragma unroll
        for (int nt = 0; nt < 3; nt++)
#pragma unroll
            for (int kt = 0; kt < 8; kt++)
                ldm_x2(bfr[nt][kt], Bs + (nb + nt * 8 + lr) * LDTB + kt * 16 + ls * 8);
    }

    // per-thread dim pair + bias registers (constant over the M-stream)
    int dim0 = D0 + (warp & 3) * 8 + ((lane & 3) << 1);
    float bR0 = bias[bnr + nb + 0 + ((lane & 3) << 1)];
    float bR1 = bias[bnr + nb + 0 + ((lane & 3) << 1) + 1];
    float bZ0 = bias[bnr + nb + 8 + ((lane & 3) << 1)];
    float bZ1 = bias[bnr + nb + 8 + ((lane & 3) << 1) + 1];
    float bN0 = bias[bnr + nb + 16 + ((lane & 3) << 1)];
    float bN1 = bias[bnr + nb + 16 + ((lane & 3) << 1) + 1];

    int buf = 0;
    while (mt < mtiles) {
        int nxt = mt + gridDim.y;
        bool pf = (nxt < mtiles);
        __nv_bfloat16* Acur = buf ? Abuf1 : Abuf0;
        __nv_bfloat16* Aalt = buf ? Abuf0 : Abuf1;
        if (pf) {
            for (int slot = tid; slot < 128 * 16; slot += GEMM_T) {
                int r = slot >> 4;
                int c8 = (slot & 15) * 8;
                cp16(Aalt + r * LDTB + c8,
                     A + (size_t)nxt * 128 * 128 + (size_t)r * 128 + c8);
            }
            asm volatile("cp.async.commit_group;");
            asm volatile("cp.async.wait_group 1;");
        } else {
            asm volatile("cp.async.wait_group 0;");
        }
        __syncthreads();

        float acc[2][3][4];
#pragma unroll
        for (int i = 0; i < 2; i++)
#pragma unroll
            for (int nt = 0; nt < 3; nt++)
#pragma unroll
                for (int e = 0; e < 4; e++) acc[i][nt][e] = 0.f;

        int q = lane >> 3;
        int arow = (q & 1) * 8 + (lane & 7);
        int acol = (q >> 1) * 8;
#pragma unroll
        for (int kt = 0; kt < 8; kt++) {
            uint32_t a[2][4];
#pragma unroll
            for (int i = 0; i < 2; i++)
                ldm_x4(a[i], Acur + (mb + i * 16 + arow) * LDTB + kt * 16 + acol);
#pragma unroll
            for (int i = 0; i < 2; i++)
#pragma unroll
                for (int nt = 0; nt < 3; nt++)
                    mma16816(acc[i][nt], a[i], bfr[nt][kt]);
        }

        // register GRU epilogue: acc[i][0]=r-gate, [1]=z, [2]=n for this thread's dims
        int bm = mt * 128;
#pragma unroll
        for (int i = 0; i < 2; i++) {
#pragma unroll
            for (int half = 0; half < 2; half++) {
                int grow = bm + mb + i * 16 + (lane >> 2) + half * 8;
                const __nv_bfloat16* ghr = gh + (size_t)grow * 384 + dim0;
                float2 hr = ldbf2(ghr);
                float2 hz = ldbf2(ghr + 128);
                float2 hn = ldbf2(ghr + 256);
                float2 h = ldbf2(hold + (size_t)grow * 128 + dim0);
                int e0 = half * 2;
                float r0 = sigf(acc[i][0][e0]     + bR0 + hr.x);
                float z0 = sigf(acc[i][1][e0]     + bZ0 + hz.x);
                float n0 = tanhapx(acc[i][2][e0]  + bN0 + r0 * hn.x);
                float o0 = (1.f - z0) * n0 + z0 * h.x;
                float r1 = sigf(acc[i][0][e0 + 1] + bR1 + hr.y);
                float z1 = sigf(acc[i][1][e0 + 1] + bZ1 + hz.y);
                float n1 = tanhapx(acc[i][2][e0 + 1] + bN1 + r1 * hn.y);
                float o1 = (1.f - z1) * n1 + z1 * h.y;
                *(__nv_bfloat162*)(outp + (size_t)grow * 128 + dim0) =
                    __floats2bfloat162_rn(o0, o1);
            }
        }
        __syncthreads();
        mt = nxt;
        buf ^= 1;
    }
}

// xb = mean over s of hb3[s]
__global__ void avg3_kernel(const __nv_bfloat16* __restrict__ hb3,
                            __nv_bfloat16* __restrict__ xb) {
    int i = blockIdx.x * blockDim.x + threadIdx.x;
    if (i >= NP * 32) return;
    size_t p = (size_t)i * 4;
    float4 a = ldbf4(hb3 + p);
    float4 b = ldbf4(hb3 + (size_t)NP * 128 + p);
    float4 c = ldbf4(hb3 + (size_t)2 * NP * 128 + p);
    float4 v;
    v.x = (a.x + b.x + c.x) * (1.0f / 3.0f);
    v.y = (a.y + b.y + c.y) * (1.0f / 3.0f);
    v.z = (a.z + b.z + c.z) * (1.0f / 3.0f);
    v.w = (a.w + b.w + c.w) * (1.0f / 3.0f);
    stbf4(xb + p, v);
}

// ---------------- pooling / MLP ----------------
__global__ void cnt_kernel(const int* __restrict__ batch, float* __restrict__ cnt, int n) {
    int i = blockIdx.x * blockDim.x + threadIdx.x;
    if (i < n) atomicAdd(&cnt[batch[i]], 1.0f);
}
__global__ void pool_kernel(const __nv_bfloat16* __restrict__ xb, const int* __restrict__ batch,
                            float* __restrict__ pool) {
    int idx = blockIdx.x * blockDim.x + threadIdx.x;
    if (idx >= NN * 32) return;
    int n = idx >> 5;
    int c = (idx & 31) * 4;
    int g = batch[n];
    float4 v = ldbf4(xb + (size_t)n * 128 + c);
    float* o = pool + (size_t)g * 128 + c;
    asm volatile("red.global.add.v4.f32 [%0], {%1,%2,%3,%4};"
                 :: "l"(o), "f"(v.x), "f"(v.y), "f"(v.z), "f"(v.w) : "memory");
}
__global__ void mlp_kernel(const float* __restrict__ pool, const float* __restrict__ cnt,
                           const float* __restrict__ pt,
                           const float* __restrict__ fc1w, const float* __restrict__ fc1b,
                           const float* __restrict__ fc2w, const float* __restrict__ fc2b,
                           const float* __restrict__ fclw, const float* __restrict__ fclb,
                           float* __restrict__ out) {
    __shared__ float h1[GG * 80];
    __shared__ float h2[GG * 80];
    int tid = threadIdx.x;
    for (int t = tid; t < GG * 80; t += blockDim.x) {
        int g = t / 80, j = t - (t / 80) * 80;
        float ic = 1.0f / fmaxf(cnt[g], 1.0f);
        float acc = fc1b[j];
        const float* w = fc1w + j * 129;
        const float* p = pool + g * 128;
        for (int k = 0; k < 128; k++) acc = fmaf(p[k] * ic, w[k], acc);
        acc = fmaf(pt[g], w[128], acc);
        h1[t] = acc > 0.f ? acc : 0.01f * acc;
    }
    __syncthreads();
    for (int t = tid; t < GG * 80; t += blockDim.x) {
        int g = t / 80, j = t - (t / 80) * 80;
        float acc = fc2b[j];
        const float* w = fc2w + j * 80;
        const float* hh = h1 + g * 80;
        for (int k = 0; k < 80; k++) acc = fmaf(hh[k], w[k], acc);
        h2[t] = acc > 0.f ? acc : 0.01f * acc;
    }
    __syncthreads();
    for (int t = tid; t < GG * OUTD; t += blockDim.x) {
        int g = t / OUTD, o = t - (t / OUTD) * OUTD;
        float acc = fclb[o];
        const float* w = fclw + o * 80;
        const float* hh = h2 + g * 80;
        for (int k = 0; k < 80; k++) acc = fmaf(hh[k], w[k], acc);
        out[t] = acc;
    }
}

// ---------------- host launcher ----------------
extern "C" void kernel_launch(void* const* d_in, const int* in_sizes, int n_in,
                              void* d_out, int out_size) {
    (void)in_sizes; (void)n_in; (void)out_size;
    const float* x     = (const float*)d_in[0];
    const int*   eidx  = (const int*)d_in[1];
    const int*   eattr = (const int*)d_in[2];
    const int*   batch = (const int*)d_in[3];
    const float* pt    = (const float*)d_in[4];
    const float* W     = (const float*)d_in[5];
    const float* wih   = (const float*)d_in[6];
    const float* whh   = (const float*)d_in[7];
    const float* bih   = (const float*)d_in[8];
    const float* bhh   = (const float*)d_in[9];
    const float* fc1w  = (const float*)d_in[10];
    const float* fc1b  = (const float*)d_in[11];
    const float* fc2w  = (const float*)d_in[12];
    const float* fc2b  = (const float*)d_in[13];
    const float* fclw  = (const float*)d_in[14];
    const float* fclb  = (const float*)d_in[15];
    float* out = (float*)d_out;

    const int* src = eidx;
    const int* dst = eidx + EE;

    float *poolp, *cntp, *bihrp;
    __nv_bfloat16 *xb, *hb3, *agg3, *gh3, *wcb, *wcb2, *wihb, *whhb, *Wb;
    int *bsrcp, *ecntp, *ecurp, *eoffp;
    cudaGetSymbolAddress((void**)&xb,    g_xb);
    cudaGetSymbolAddress((void**)&hb3,   g_hb3);
    cudaGetSymbolAddress((void**)&agg3,  g_agg3);
    cudaGetSymbolAddress((void**)&gh3,   g_gh3);
    cudaGetSymbolAddress((void**)&wcb,   g_wcb);
    cudaGetSymbolAddress((void**)&wcb2,  g_wcb2);
    cudaGetSymbolAddress((void**)&wihb,  g_wihb);
    cudaGetSymbolAddress((void**)&whhb,  g_whhb);
    cudaGetSymbolAddress((void**)&Wb,    g_Wb);
    cudaGetSymbolAddress((void**)&bihrp, g_bihr);
    cudaGetSymbolAddress((void**)&poolp, g_pool);
    cudaGetSymbolAddress((void**)&cntp,  g_cnt);
    cudaGetSymbolAddress((void**)&bsrcp, g_bsrc);
    cudaGetSymbolAddress((void**)&ecntp, g_ecnt);
    cudaGetSymbolAddress((void**)&ecurp, g_ecur);
    cudaGetSymbolAddress((void**)&eoffp, g_eoff);

    cudaFuncSetAttribute(bf16_gemm, cudaFuncAttributeMaxDynamicSharedMemorySize, BG_SMEM);
    cudaFuncSetAttribute(gemm_gru, cudaFuncAttributeMaxDynamicSharedMemorySize, FG_SMEM);

    const int TB = 256;
    dim3 g3(3, 16, 3);
    dim3 fg(4, 12, 3);

    cudaStream_t s2;
    cudaStreamCreateWithFlags(&s2, cudaStreamNonBlocking);
    cudaEvent_t evX, evG[4], evF[4];
    cudaEventCreateWithFlags(&evX, cudaEventDisableTiming);
    for (int k = 0; k < 4; k++) {
        cudaEventCreateWithFlags(&evG[k], cudaEventDisableTiming);
        cudaEventCreateWithFlags(&evF[k], cudaEventDisableTiming);
    }

    // ---- prologue ----
    copy_pad_kernel<<<(NP * 32 + TB - 1) / TB, TB>>>(x, xb);                    // main 0
    cudaEventRecord(evX, 0);
    cvt_bf16_kernel<<<(SS * 384 * 32 + TB - 1) / TB, TB>>>(whh, whhb,
                                                           SS * 384 * 32);      // main 1
    zero2_ints<<<(NPS + TB - 1) / TB, TB, 0, s2>>>(ecntp, ecurp, NPS);          // s2
    // main idx 3 (PROFILED): gh GEMM for superstep (0,0)
    {
        GemmArgs ga;
        for (int s = 0; s < 3; s++) {
            ga.A[s] = xb;
            ga.B[s] = whhb + (size_t)s * 384 * 128;
            ga.bias[s] = bhh + s * 384;
            ga.C[s] = gh3 + (size_t)s * NP * 384;
        }
        bf16_gemm<<<g3, GEMM_T, BG_SMEM>>>(ga, 384, M_TILES);
    }
    // s2: CSR + first gather
    ecount_kernel<<<(EE + TB - 1) / TB, TB, 0, s2>>>(dst, eattr, ecntp, EE);
    scan_kernel<<<1, 1024, 0, s2>>>(ecntp, eoffp, NPS);
    fill_kernel<<<(EE + TB - 1) / TB, TB, 0, s2>>>(src, dst, eattr, eoffp, ecurp, bsrcp, EE);
    cudaStreamWaitEvent(s2, evX, 0);
    {
        Feat3 f; f.p[0] = xb; f.p[1] = xb; f.p[2] = xb;
        gather3_kernel<<<(SS * NP * 32 + TB - 1) / TB, TB, 0, s2>>>(eoffp, bsrcp, f, agg3);
    }
    cudaEventRecord(evG[0], s2);
    // main: weight prep (block-interleaved)
    cvt_wih_il_kernel<<<(SS * 384 * 32 + TB - 1) / TB, TB>>>(wih, wihb);
    cvt_bf16_kernel<<<(SS * 2 * 128 * 32 + TB - 1) / TB, TB>>>(W, Wb, SS * 2 * 128 * 32);
    bihr_kernel<<<(SS * 384 + TB - 1) / TB, TB>>>(bih, bihrp);
    {
        GemmArgs ga;
        for (int z = 0; z < 6; z++) {
            int s = z / 2, i = z % 2;
            ga.A[z] = wihb + (size_t)s * 384 * 128;
            ga.B[z] = Wb + (size_t)(s * 2 + i) * 128 * 128;
            ga.bias[z] = nullptr;
            ga.C[z] = (i == 0 ? wcb : wcb2) + (size_t)s * 384 * 128;
        }
        bf16_gemm<<<dim3(1, 3, 6), GEMM_T, BG_SMEM>>>(ga, 128, 3);
    }

    // ---- main loop: 4 supersteps ----
    int step = 0;
    for (int pass = 0; pass < 2; pass++) {
        for (int i = 0; i < 2; i++, step++) {
            if (step > 0) {
                cudaEventRecord(evF[step], 0);
                cudaStreamWaitEvent(s2, evF[step], 0);
                Feat3 f;
                if (i == 0) { f.p[0] = xb; f.p[1] = xb; f.p[2] = xb; }
                else {
                    f.p[0] = hb3;
                    f.p[1] = hb3 + (size_t)NP * 128;
                    f.p[2] = hb3 + (size_t)2 * NP * 128;
                }
                gather3_kernel<<<(SS * NP * 32 + TB - 1) / TB, TB, 0, s2>>>(
                    eoffp, bsrcp, f, agg3);
                cudaEventRecord(evG[step], s2);
                GemmArgs ga;
                for (int s = 0; s < 3; s++) {
                    ga.A[s] = (i == 0) ? xb : (hb3 + (size_t)s * NP * 128);
                    ga.B[s] = whhb + (size_t)s * 384 * 128;
                    ga.bias[s] = bhh + s * 384;
                    ga.C[s] = gh3 + (size_t)s * NP * 384;
                }
                bf16_gemm<<<g3, GEMM_T, BG_SMEM>>>(ga, 384, M_TILES);
            }
            cudaStreamWaitEvent(0, evG[step], 0);
            {
                FusedArgs fa;
                for (int s = 0; s < 3; s++) {
                    fa.A[s] = agg3 + (size_t)s * NP * 128;
                    fa.B[s] = (i == 0 ? wcb : wcb2) + (size_t)s * 384 * 128;
                    fa.gh[s] = gh3 + (size_t)s * NP * 384;
                    fa.hold[s] = (i == 0) ? xb : (hb3 + (size_t)s * NP * 128);
                    fa.out[s] = hb3 + (size_t)s * NP * 128;
                    fa.bias[s] = bihrp + s * 384;
                }
                gemm_gru<<<fg, GEMM_T, FG_SMEM>>>(fa, M_TILES);
            }
            if (i == 1)
                avg3_kernel<<<(NP * 32 + TB - 1) / TB, TB>>>(hb3, xb);
        }
    }

    // ---- pooling + MLP ----
    zero_kernel<<<(GG * DD / 4 + TB - 1) / TB, TB>>>(poolp, GG * DD / 4);
    zero_kernel<<<1, GG / 4>>>(cntp, GG / 4);
    cnt_kernel<<<(NN + TB - 1) / TB, TB>>>(batch, cntp, NN);
    pool_kernel<<<(NN * 32 + TB - 1) / TB, TB>>>(xb, batch, poolp);
    mlp_kernel<<<1, 256>>>(poolp, cntp, pt, fc1w, fc1b, fc2w, fc2b, fclw, fclb, out);

    cudaStreamCaptureStatus cap = cudaStreamCaptureStatusNone;
    cudaStreamIsCapturing(0, &cap);
    if (cap == cudaStreamCaptureStatusNone) {
        cudaEventDestroy(evX);
        for (int k = 0; k < 4; k++) { cudaEventDestroy(evG[k]); cudaEventDestroy(evF[k]); }
        cudaStreamDestroy(s2);
    }
}

// round 16
// speedup vs baseline: 1.0817x; 1.0817x over previous
#include <cuda_runtime.h>
#include <cuda_bf16.h>
#include <math.h>
#include <stdint.h>

#define NN 100000
#define NP 100096
#define EE 600000
#define DD 128
#define SS 3
#define GG 64
#define OUTD 2
#define NPS (SS * NP)
#define M_TILES (NP / 128)        // 782

// ---------------- device scratch ----------------
__device__ __nv_bfloat16 g_xb[NP * DD];
__device__ __nv_bfloat16 g_hb3[SS * NP * DD];
__device__ __nv_bfloat16 g_agg3[SS * NP * DD];
__device__ __nv_bfloat16 g_gh3[SS * NP * 3 * DD];
__device__ __nv_bfloat16 g_wcb[SS * 3 * DD * DD];     // block-interleaved combined, i=0
__device__ __nv_bfloat16 g_wcb2[SS * 3 * DD * DD];    // i=1
__device__ __nv_bfloat16 g_wihb[SS * 3 * DD * DD];    // block-interleaved rows
__device__ __nv_bfloat16 g_whhb[SS * 3 * DD * DD];
__device__ __nv_bfloat16 g_Wb[SS * 2 * DD * DD];
__device__ float g_bihr[SS * 3 * DD];                 // block-interleaved bias
__device__ float g_pool[GG * DD];
__device__ float g_cnt[GG];
__device__ int   g_bsrc[EE];
__device__ int   g_ecnt[NPS];
__device__ int   g_ecur[NPS];
__device__ int   g_eoff[NPS + 1];

// ---------------- tiny utils ----------------
__global__ void zero_kernel(float* __restrict__ p, int n4) {
    int i = blockIdx.x * blockDim.x + threadIdx.x;
    if (i < n4) ((float4*)p)[i] = make_float4(0.f, 0.f, 0.f, 0.f);
}
__global__ void copy_pad_kernel(const float* __restrict__ x, __nv_bfloat16* __restrict__ xb) {
    int i = blockIdx.x * blockDim.x + threadIdx.x;
    if (i >= NP * 32) return;
    int n = i >> 5;
    float4 v = make_float4(0.f, 0.f, 0.f, 0.f);
    if (n < NN) v = ((const float4*)x)[i];
    *(__nv_bfloat162*)(xb + (size_t)i * 4)     = __floats2bfloat162_rn(v.x, v.y);
    *(__nv_bfloat162*)(xb + (size_t)i * 4 + 2) = __floats2bfloat162_rn(v.z, v.w);
}
__global__ void cvt_bf16_kernel(const float* __restrict__ src,
                                __nv_bfloat16* __restrict__ dst, int n4) {
    int i = blockIdx.x * blockDim.x + threadIdx.x;
    if (i >= n4) return;
    float4 v = ((const float4*)src)[i];
    *(__nv_bfloat162*)(dst + (size_t)i * 4)     = __floats2bfloat162_rn(v.x, v.y);
    *(__nv_bfloat162*)(dst + (size_t)i * 4 + 2) = __floats2bfloat162_rn(v.z, v.w);
}
// wih rows: j = g*128+d  ->  jil = (d/8)*24 + g*8 + (d%8)   (per s), fp32 -> bf16
__global__ void cvt_wih_il_kernel(const float* __restrict__ wih,
                                  __nv_bfloat16* __restrict__ dst) {
    int i = blockIdx.x * blockDim.x + threadIdx.x;
    if (i >= SS * 384 * 32) return;
    int s = i / (384 * 32);
    int rem = i - s * 384 * 32;
    int j = rem >> 5;
    int k4 = (rem & 31) * 4;
    int g = j >> 7;
    int d = j & 127;
    int jil = (d >> 3) * 24 + g * 8 + (d & 7);
    float4 v = *(const float4*)(wih + (size_t)(s * 384 + j) * 128 + k4);
    __nv_bfloat16* o = dst + (size_t)(s * 384 + jil) * 128 + k4;
    *(__nv_bfloat162*)(o)     = __floats2bfloat162_rn(v.x, v.y);
    *(__nv_bfloat162*)(o + 2) = __floats2bfloat162_rn(v.z, v.w);
}
__global__ void bihr_kernel(const float* __restrict__ bih, float* __restrict__ bihr) {
    int i = blockIdx.x * blockDim.x + threadIdx.x;
    if (i >= SS * 384) return;
    int s = i / 384;
    int j = i - s * 384;
    int g = j >> 7;
    int d = j & 127;
    int jil = (d >> 3) * 24 + g * 8 + (d & 7);
    bihr[s * 384 + jil] = bih[i];
}
__global__ void zero2_ints(int* __restrict__ a, int* __restrict__ b, int n) {
    int i = blockIdx.x * blockDim.x + threadIdx.x;
    if (i < n) { a[i] = 0; b[i] = 0; }
}

// ---------------- CSR build ----------------
__global__ void ecount_kernel(const int* __restrict__ dst, const int* __restrict__ attr,
                              int* __restrict__ cnt, int E) {
    int e = blockIdx.x * blockDim.x + threadIdx.x;
    if (e < E) atomicAdd(&cnt[attr[e] * NP + dst[e]], 1);
}
__global__ void scan_kernel(const int* __restrict__ cnt, int* __restrict__ off, int n) {
    __shared__ int ssum[1024];
    int t = threadIdx.x;
    int per = (n + 1023) / 1024;
    int b0 = t * per;
    int b1 = b0 + per; if (b1 > n) b1 = n; if (b0 > n) b0 = n;
    int s = 0;
    for (int i = b0; i < b1; i++) s += cnt[i];
    ssum[t] = s;
    __syncthreads();
    for (int d = 1; d < 1024; d <<= 1) {
        int v = (t >= d) ? ssum[t - d] : 0;
        __syncthreads();
        ssum[t] += v;
        __syncthreads();
    }
    int run = (t == 0) ? 0 : ssum[t - 1];
    if (t == 1023) off[n] = ssum[1023];
    for (int i = b0; i < b1; i++) { off[i] = run; run += cnt[i]; }
}
__global__ void fill_kernel(const int* __restrict__ src, const int* __restrict__ dst,
                            const int* __restrict__ attr, const int* __restrict__ off,
                            int* __restrict__ cur, int* __restrict__ bsrc, int E) {
    int e = blockIdx.x * blockDim.x + threadIdx.x;
    if (e >= E) return;
    int idx = attr[e] * NP + dst[e];
    int pos = off[idx] + atomicAdd(&cur[idx], 1);
    bsrc[pos] = src[e];
}

// ---------------- gather all 3 types ----------------
struct Feat3 { const __nv_bfloat16* p[3]; };

__global__ void gather3_kernel(const int* __restrict__ off, const int* __restrict__ bsrc,
                               Feat3 f, __nv_bfloat16* __restrict__ agg3) {
    int w = (blockIdx.x * blockDim.x + threadIdx.x) >> 5;
    int lane = threadIdx.x & 31;
    if (w >= SS * NP) return;
    int s = w / NP;
    const __nv_bfloat16* feat = f.p[s];
    int e0 = off[w], e1 = off[w + 1];
    float a0 = 0.f, a1 = 0.f, a2 = 0.f, a3 = 0.f;
    for (int e = e0; e < e1; e++) {
        int sn = bsrc[e];
        uint2 u = *(const uint2*)(feat + (size_t)sn * DD + lane * 4);
        __nv_bfloat162 p0 = *(__nv_bfloat162*)&u.x;
        __nv_bfloat162 p1 = *(__nv_bfloat162*)&u.y;
        float2 f0 = __bfloat1622float2(p0), f1 = __bfloat1622float2(p1);
        a0 += f0.x; a1 += f0.y; a2 += f1.x; a3 += f1.y;
    }
    if (e1 > e0) {
        float inv = 1.0f / (float)(e1 - e0);
        a0 *= inv; a1 *= inv; a2 *= inv; a3 *= inv;
    }
    uint2 o;
    *(__nv_bfloat162*)&o.x = __floats2bfloat162_rn(a0, a1);
    *(__nv_bfloat162*)&o.y = __floats2bfloat162_rn(a2, a3);
    *(uint2*)(agg3 + (size_t)w * DD + lane * 4) = o;
}

// ---------------- mma helpers ----------------
#define LDTB 136
__device__ __forceinline__ void cp16(void* s, const void* g) {
    uint32_t sa = (uint32_t)__cvta_generic_to_shared(s);
    asm volatile("cp.async.cg.shared.global [%0], [%1], 16;" :: "r"(sa), "l"(g));
}
__device__ __forceinline__ void ldm_x4(uint32_t* r, const __nv_bfloat16* p) {
    uint32_t sa = (uint32_t)__cvta_generic_to_shared(p);
    asm volatile("ldmatrix.sync.aligned.m8n8.x4.shared.b16 {%0,%1,%2,%3}, [%4];"
                 : "=r"(r[0]), "=r"(r[1]), "=r"(r[2]), "=r"(r[3]) : "r"(sa));
}
__device__ __forceinline__ void ldm_x2(uint32_t* r, const __nv_bfloat16* p) {
    uint32_t sa = (uint32_t)__cvta_generic_to_shared(p);
    asm volatile("ldmatrix.sync.aligned.m8n8.x2.shared.b16 {%0,%1}, [%2];"
                 : "=r"(r[0]), "=r"(r[1]) : "r"(sa));
}
__device__ __forceinline__ void mma16816(float* c, const uint32_t* a, const uint32_t* b) {
    asm volatile(
        "mma.sync.aligned.m16n8k16.row.col.f32.bf16.bf16.f32 "
        "{%0,%1,%2,%3}, {%4,%5,%6,%7}, {%8,%9}, {%0,%1,%2,%3};"
        : "+f"(c[0]), "+f"(c[1]), "+f"(c[2]), "+f"(c[3])
        : "r"(a[0]), "r"(a[1]), "r"(a[2]), "r"(a[3]), "r"(b[0]), "r"(b[1]));
}
__device__ __forceinline__ float tanhapx(float x) {
    float y;
    asm("tanh.approx.f32 %0, %1;" : "=f"(y) : "f"(x));
    return y;
}
__device__ __forceinline__ float sigf(float x) {
    return 0.5f * tanhapx(0.5f * x) + 0.5f;
}
__device__ __forceinline__ float4 ldbf4(const __nv_bfloat16* p) {
    uint2 u = *(const uint2*)p;
    __nv_bfloat162 a = *(__nv_bfloat162*)&u.x;
    __nv_bfloat162 b = *(__nv_bfloat162*)&u.y;
    float2 fa = __bfloat1622float2(a), fb = __bfloat1622float2(b);
    return make_float4(fa.x, fa.y, fb.x, fb.y);
}
__device__ __forceinline__ void stbf4(__nv_bfloat16* p, float4 v) {
    uint2 u;
    *(__nv_bfloat162*)&u.x = __floats2bfloat162_rn(v.x, v.y);
    *(__nv_bfloat162*)&u.y = __floats2bfloat162_rn(v.z, v.w);
    *(uint2*)p = u;
}

// ========== plain weights-stationary GEMM (gh + wc), R12 core ==========
#define SMB_B (128 * LDTB * 2)
#define SMB_A (128 * LDTB * 2)
#define BG_SMEM (SMB_B + 2 * SMB_A)  // 104448
#define GEMM_T 512

struct GemmArgs {
    const __nv_bfloat16* A[6];
    const __nv_bfloat16* B[6];
    const float* bias[6];
    __nv_bfloat16* C[6];
};

__global__ void __launch_bounds__(GEMM_T, 1)
bf16_gemm(GemmArgs ga, int J, int mtiles) {
    int z = blockIdx.z;
    const __nv_bfloat16* A = ga.A[z];
    const __nv_bfloat16* B = ga.B[z];
    const float* bias = ga.bias[z];
    __nv_bfloat16* C = ga.C[z];

    extern __shared__ char smx[];
    __nv_bfloat16* Bs = (__nv_bfloat16*)smx;
    __nv_bfloat16* Abuf0 = (__nv_bfloat16*)(smx + SMB_B);
    __nv_bfloat16* Abuf1 = (__nv_bfloat16*)(smx + SMB_B + SMB_A);

    int tid = threadIdx.x;
    int warp = tid >> 5;
    int lane = tid & 31;
    int mb = (warp >> 2) * 32;
    int nb = (warp & 3) * 32;
    int bn = blockIdx.x * 128;

    int mt = blockIdx.y;
    if (mt >= mtiles) return;

    for (int slot = tid; slot < 128 * 16; slot += GEMM_T) {
        int r = slot >> 4;
        int c8 = (slot & 15) * 8;
        cp16(Bs + r * LDTB + c8, B + (size_t)(bn + r) * 128 + c8);
    }
    asm volatile("cp.async.commit_group;");
    for (int slot = tid; slot < 128 * 16; slot += GEMM_T) {
        int r = slot >> 4;
        int c8 = (slot & 15) * 8;
        cp16(Abuf0 + r * LDTB + c8, A + (size_t)mt * 128 * 128 + (size_t)r * 128 + c8);
    }
    asm volatile("cp.async.commit_group;");
    asm volatile("cp.async.wait_group 1;");
    __syncthreads();

    uint32_t bf[4][8][2];
    {
        int lr = lane & 7;
        int ls = (lane >> 3) & 1;
#pragma unroll
        for (int nt = 0; nt < 4; nt++)
#pragma unroll
            for (int kt = 0; kt < 8; kt++)
                ldm_x2(bf[nt][kt], Bs + (nb + nt * 8 + lr) * LDTB + kt * 16 + ls * 8);
    }

    int buf = 0;
    while (mt < mtiles) {
        int nxt = mt + gridDim.y;
        bool pf = (nxt < mtiles);
        __nv_bfloat16* Acur = buf ? Abuf1 : Abuf0;
        __nv_bfloat16* Aalt = buf ? Abuf0 : Abuf1;
        if (pf) {
            for (int slot = tid; slot < 128 * 16; slot += GEMM_T) {
                int r = slot >> 4;
                int c8 = (slot & 15) * 8;
                cp16(Aalt + r * LDTB + c8,
                     A + (size_t)nxt * 128 * 128 + (size_t)r * 128 + c8);
            }
            asm volatile("cp.async.commit_group;");
            asm volatile("cp.async.wait_group 1;");
        } else {
            asm volatile("cp.async.wait_group 0;");
        }
        __syncthreads();

        float acc[2][4][4];
#pragma unroll
        for (int i = 0; i < 2; i++)
#pragma unroll
            for (int nt = 0; nt < 4; nt++)
#pragma unroll
                for (int e = 0; e < 4; e++) acc[i][nt][e] = 0.f;

        int q = lane >> 3;
        int arow = (q & 1) * 8 + (lane & 7);
        int acol = (q >> 1) * 8;
#pragma unroll
        for (int kt = 0; kt < 8; kt++) {
            uint32_t a[2][4];
#pragma unroll
            for (int i = 0; i < 2; i++)
                ldm_x4(a[i], Acur + (mb + i * 16 + arow) * LDTB + kt * 16 + acol);
#pragma unroll
            for (int i = 0; i < 2; i++)
#pragma unroll
                for (int nt = 0; nt < 4; nt++)
                    mma16816(acc[i][nt], a[i], bf[nt][kt]);
        }

        int bm = mt * 128;
#pragma unroll
        for (int i = 0; i < 2; i++) {
#pragma unroll
            for (int nt = 0; nt < 4; nt++) {
                int r0 = bm + mb + i * 16 + (lane >> 2);
                int cc = bn + nb + nt * 8 + ((lane & 3) << 1);
                float b0v = 0.f, b1v = 0.f;
                if (bias != nullptr) { b0v = bias[cc]; b1v = bias[cc + 1]; }
                *(__nv_bfloat162*)(C + (size_t)r0 * J + cc) =
                    __floats2bfloat162_rn(acc[i][nt][0] + b0v, acc[i][nt][1] + b1v);
                *(__nv_bfloat162*)(C + (size_t)(r0 + 8) * J + cc) =
                    __floats2bfloat162_rn(acc[i][nt][2] + b0v, acc[i][nt][3] + b1v);
            }
        }
        __syncthreads();
        mt = nxt;
        buf ^= 1;
    }
}

// ========== fused gi-GEMM + GRU (block-interleaved Wc, de-interleaved staging) ==========
// Stripe = 96 cols = 4 dim-blocks x (3 gates x 8 dims). Warp tile 32(M) x 24(N).
// Epilogue stages gi de-interleaved in smem ([row][gate*32+dim]); GRU reads vector LDS.
#define SMB_B2 (96 * LDTB * 2)           // 26112
#define FG_SMEM (SMB_B2 + 2 * SMB_A)     // 95744
#define STRC 104

struct FusedArgs {
    const __nv_bfloat16* A[3];
    const __nv_bfloat16* B[3];
    const __nv_bfloat16* gh[3];
    const __nv_bfloat16* hold[3];
    __nv_bfloat16* out[3];
    const float* bias[3];
};

__global__ void __launch_bounds__(GEMM_T, 1)
gemm_gru(FusedArgs fa, int mtiles) {
    int s = blockIdx.z;
    const __nv_bfloat16* A = fa.A[s];
    const __nv_bfloat16* B = fa.B[s];
    const __nv_bfloat16* gh = fa.gh[s];
    const __nv_bfloat16* hold = fa.hold[s];
    __nv_bfloat16* outp = fa.out[s];
    const float* bias = fa.bias[s];

    extern __shared__ char smx[];
    __nv_bfloat16* Bs = (__nv_bfloat16*)smx;
    __nv_bfloat16* Abuf0 = (__nv_bfloat16*)(smx + SMB_B2);
    __nv_bfloat16* Abuf1 = (__nv_bfloat16*)(smx + SMB_B2 + SMB_A);

    int tid = threadIdx.x;
    int warp = tid >> 5;
    int lane = tid & 31;
    int mb = (warp >> 2) * 32;
    int nb = (warp & 3) * 24;      // dim-block band
    int bnr = blockIdx.x * 96;
    int D0 = blockIdx.x * 32;

    int mt = blockIdx.y;
    if (mt >= mtiles) return;

    for (int slot = tid; slot < 96 * 16; slot += GEMM_T) {
        int r = slot >> 4;
        int c8 = (slot & 15) * 8;
        cp16(Bs + r * LDTB + c8, B + (size_t)(bnr + r) * 128 + c8);
    }
    asm volatile("cp.async.commit_group;");
    for (int slot = tid; slot < 128 * 16; slot += GEMM_T) {
        int r = slot >> 4;
        int c8 = (slot & 15) * 8;
        cp16(Abuf0 + r * LDTB + c8, A + (size_t)mt * 128 * 128 + (size_t)r * 128 + c8);
    }
    asm volatile("cp.async.commit_group;");
    asm volatile("cp.async.wait_group 1;");
    __syncthreads();

    uint32_t bfr[3][8][2];
    {
        int lr = lane & 7;
        int ls = (lane >> 3) & 1;
#pragma unroll
        for (int nt = 0; nt < 3; nt++)
#pragma unroll
            for (int kt = 0; kt < 8; kt++)
                ldm_x2(bfr[nt][kt], Bs + (nb + nt * 8 + lr) * LDTB + kt * 16 + ls * 8);
    }

    // hoisted per-gate bias for this thread's dim pair (block interleave: gate g at nb+g*8)
    float bg0[3], bg1[3];
#pragma unroll
    for (int g = 0; g < 3; g++) {
        bg0[g] = bias[bnr + nb + g * 8 + ((lane & 3) << 1)];
        bg1[g] = bias[bnr + nb + g * 8 + ((lane & 3) << 1) + 1];
    }
    int dcol = (warp & 3) * 8 + ((lane & 3) << 1);   // dim within 32-block for staging

    int buf = 0;
    while (mt < mtiles) {
        int nxt = mt + gridDim.y;
        bool pf = (nxt < mtiles);
        __nv_bfloat16* Acur = buf ? Abuf1 : Abuf0;
        __nv_bfloat16* Aalt = buf ? Abuf0 : Abuf1;
        if (pf) {
            for (int slot = tid; slot < 128 * 16; slot += GEMM_T) {
                int r = slot >> 4;
                int c8 = (slot & 15) * 8;
                cp16(Aalt + r * LDTB + c8,
                     A + (size_t)nxt * 128 * 128 + (size_t)r * 128 + c8);
            }
            asm volatile("cp.async.commit_group;");
            asm volatile("cp.async.wait_group 1;");
        } else {
            asm volatile("cp.async.wait_group 0;");
        }
        __syncthreads();

        float acc[2][3][4];
#pragma unroll
        for (int i = 0; i < 2; i++)
#pragma unroll
            for (int nt = 0; nt < 3; nt++)
#pragma unroll
                for (int e = 0; e < 4; e++) acc[i][nt][e] = 0.f;

        int q = lane >> 3;
        int arow = (q & 1) * 8 + (lane & 7);
        int acol = (q >> 1) * 8;
#pragma unroll
        for (int kt = 0; kt < 8; kt++) {
            uint32_t a[2][4];
#pragma unroll
            for (int i = 0; i < 2; i++)
                ldm_x4(a[i], Acur + (mb + i * 16 + arow) * LDTB + kt * 16 + acol);
#pragma unroll
            for (int i = 0; i < 2; i++)
#pragma unroll
                for (int nt = 0; nt < 3; nt++)
                    mma16816(acc[i][nt], a[i], bfr[nt][kt]);
        }
        __syncthreads();   // all Acur reads done

        // stage gi (+bias) de-interleaved: Cs[row][gate*32 + dim]
        __nv_bfloat16* Cs = Acur;
#pragma unroll
        for (int i = 0; i < 2; i++) {
#pragma unroll
            for (int nt = 0; nt < 3; nt++) {
                int r0 = mb + i * 16 + (lane >> 2);
                int cc = nt * 32 + dcol;
                *(__nv_bfloat162*)(Cs + r0 * STRC + cc) =
                    __floats2bfloat162_rn(acc[i][nt][0] + bg0[nt], acc[i][nt][1] + bg1[nt]);
                *(__nv_bfloat162*)(Cs + (r0 + 8) * STRC + cc) =
                    __floats2bfloat162_rn(acc[i][nt][2] + bg0[nt], acc[i][nt][3] + bg1[nt]);
            }
        }
        __syncthreads();

        // GRU: 128 rows x 32 dims, vector LDS reads (4 dims contiguous)
        int bm = mt * 128;
#pragma unroll
        for (int it = 0; it < 2; it++) {
            int g = tid + it * GEMM_T;          // 0..1023
            int row = g >> 3;
            int d4 = (g & 7) << 2;
            int grow = bm + row;
            const __nv_bfloat16* crow = Cs + row * STRC;
            float4 ir  = ldbf4(crow + d4);
            float4 iz  = ldbf4(crow + 32 + d4);
            float4 in4 = ldbf4(crow + 64 + d4);
            const __nv_bfloat16* ghr = gh + (size_t)grow * 384 + D0 + d4;
            float4 hr = ldbf4(ghr);
            float4 hz = ldbf4(ghr + 128);
            float4 hn = ldbf4(ghr + 256);
            float4 h = ldbf4(hold + (size_t)grow * 128 + D0 + d4);
            float4 o;
            { float r = sigf(ir.x + hr.x), z = sigf(iz.x + hz.x);
              float nn = tanhapx(in4.x + r * hn.x); o.x = (1.f - z) * nn + z * h.x; }
            { float r = sigf(ir.y + hr.y), z = sigf(iz.y + hz.y);
              float nn = tanhapx(in4.y + r * hn.y); o.y = (1.f - z) * nn + z * h.y; }
            { float r = sigf(ir.z + hr.z), z = sigf(iz.z + hz.z);
              float nn = tanhapx(in4.z + r * hn.z); o.z = (1.f - z) * nn + z * h.z; }
            { float r = sigf(ir.w + hr.w), z = sigf(iz.w + hz.w);
              float nn = tanhapx(in4.w + r * hn.w); o.w = (1.f - z) * nn + z * h.w; }
            stbf4(outp + (size_t)grow * 128 + D0 + d4, o);
        }
        __syncthreads();
        mt = nxt;
        buf ^= 1;
    }
}

// xb = mean over s of hb3[s]
__global__ void avg3_kernel(const __nv_bfloat16* __restrict__ hb3,
                            __nv_bfloat16* __restrict__ xb) {
    int i = blockIdx.x * blockDim.x + threadIdx.x;
    if (i >= NP * 32) return;
    size_t p = (size_t)i * 4;
    float4 a = ldbf4(hb3 + p);
    float4 b = ldbf4(hb3 + (size_t)NP * 128 + p);
    float4 c = ldbf4(hb3 + (size_t)2 * NP * 128 + p);
    float4 v;
    v.x = (a.x + b.x + c.x) * (1.0f / 3.0f);
    v.y = (a.y + b.y + c.y) * (1.0f / 3.0f);
    v.z = (a.z + b.z + c.z) * (1.0f / 3.0f);
    v.w = (a.w + b.w + c.w) * (1.0f / 3.0f);
    stbf4(xb + p, v);
}

// ---------------- pooling / MLP ----------------
__global__ void cnt_kernel(const int* __restrict__ batch, float* __restrict__ cnt, int n) {
    int i = blockIdx.x * blockDim.x + threadIdx.x;
    if (i < n) atomicAdd(&cnt[batch[i]], 1.0f);
}
__global__ void pool_kernel(const __nv_bfloat16* __restrict__ xb, const int* __restrict__ batch,
                            float* __restrict__ pool) {
    int idx = blockIdx.x * blockDim.x + threadIdx.x;
    if (idx >= NN * 32) return;
    int n = idx >> 5;
    int c = (idx & 31) * 4;
    int g = batch[n];
    float4 v = ldbf4(xb + (size_t)n * 128 + c);
    float* o = pool + (size_t)g * 128 + c;
    asm volatile("red.global.add.v4.f32 [%0], {%1,%2,%3,%4};"
                 :: "l"(o), "f"(v.x), "f"(v.y), "f"(v.z), "f"(v.w) : "memory");
}
__global__ void mlp_kernel(const float* __restrict__ pool, const float* __restrict__ cnt,
                           const float* __restrict__ pt,
                           const float* __restrict__ fc1w, const float* __restrict__ fc1b,
                           const float* __restrict__ fc2w, const float* __restrict__ fc2b,
                           const float* __restrict__ fclw, const float* __restrict__ fclb,
                           float* __restrict__ out) {
    __shared__ float h1[GG * 80];
    __shared__ float h2[GG * 80];
    int tid = threadIdx.x;
    for (int t = tid; t < GG * 80; t += blockDim.x) {
        int g = t / 80, j = t - (t / 80) * 80;
        float ic = 1.0f / fmaxf(cnt[g], 1.0f);
        float acc = fc1b[j];
        const float* w = fc1w + j * 129;
        const float* p = pool + g * 128;
        for (int k = 0; k < 128; k++) acc = fmaf(p[k] * ic, w[k], acc);
        acc = fmaf(pt[g], w[128], acc);
        h1[t] = acc > 0.f ? acc : 0.01f * acc;
    }
    __syncthreads();
    for (int t = tid; t < GG * 80; t += blockDim.x) {
        int g = t / 80, j = t - (t / 80) * 80;
        float acc = fc2b[j];
        const float* w = fc2w + j * 80;
        const float* hh = h1 + g * 80;
        for (int k = 0; k < 80; k++) acc = fmaf(hh[k], w[k], acc);
        h2[t] = acc > 0.f ? acc : 0.01f * acc;
    }
    __syncthreads();
    for (int t = tid; t < GG * OUTD; t += blockDim.x) {
        int g = t / OUTD, o = t - (t / OUTD) * OUTD;
        float acc = fclb[o];
        const float* w = fclw + o * 80;
        const float* hh = h2 + g * 80;
        for (int k = 0; k < 80; k++) acc = fmaf(hh[k], w[k], acc);
        out[t] = acc;
    }
}

// ---------------- host launcher ----------------
extern "C" void kernel_launch(void* const* d_in, const int* in_sizes, int n_in,
                              void* d_out, int out_size) {
    (void)in_sizes; (void)n_in; (void)out_size;
    const float* x     = (const float*)d_in[0];
    const int*   eidx  = (const int*)d_in[1];
    const int*   eattr = (const int*)d_in[2];
    const int*   batch = (const int*)d_in[3];
    const float* pt    = (const float*)d_in[4];
    const float* W     = (const float*)d_in[5];
    const float* wih   = (const float*)d_in[6];
    const float* whh   = (const float*)d_in[7];
    const float* bih   = (const float*)d_in[8];
    const float* bhh   = (const float*)d_in[9];
    const float* fc1w  = (const float*)d_in[10];
    const float* fc1b  = (const float*)d_in[11];
    const float* fc2w  = (const float*)d_in[12];
    const float* fc2b  = (const float*)d_in[13];
    const float* fclw  = (const float*)d_in[14];
    const float* fclb  = (const float*)d_in[15];
    float* out = (float*)d_out;

    const int* src = eidx;
    const int* dst = eidx + EE;

    float *poolp, *cntp, *bihrp;
    __nv_bfloat16 *xb, *hb3, *agg3, *gh3, *wcb, *wcb2, *wihb, *whhb, *Wb;
    int *bsrcp, *ecntp, *ecurp, *eoffp;
    cudaGetSymbolAddress((void**)&xb,    g_xb);
    cudaGetSymbolAddress((void**)&hb3,   g_hb3);
    cudaGetSymbolAddress((void**)&agg3,  g_agg3);
    cudaGetSymbolAddress((void**)&gh3,   g_gh3);
    cudaGetSymbolAddress((void**)&wcb,   g_wcb);
    cudaGetSymbolAddress((void**)&wcb2,  g_wcb2);
    cudaGetSymbolAddress((void**)&wihb,  g_wihb);
    cudaGetSymbolAddress((void**)&whhb,  g_whhb);
    cudaGetSymbolAddress((void**)&Wb,    g_Wb);
    cudaGetSymbolAddress((void**)&bihrp, g_bihr);
    cudaGetSymbolAddress((void**)&poolp, g_pool);
    cudaGetSymbolAddress((void**)&cntp,  g_cnt);
    cudaGetSymbolAddress((void**)&bsrcp, g_bsrc);
    cudaGetSymbolAddress((void**)&ecntp, g_ecnt);
    cudaGetSymbolAddress((void**)&ecurp, g_ecur);
    cudaGetSymbolAddress((void**)&eoffp, g_eoff);

    cudaFuncSetAttribute(bf16_gemm, cudaFuncAttributeMaxDynamicSharedMemorySize, BG_SMEM);
    cudaFuncSetAttribute(gemm_gru, cudaFuncAttributeMaxDynamicSharedMemorySize, FG_SMEM);

    const int TB = 256;
    dim3 g3(3, 16, 3);
    dim3 fg(4, 12, 3);

    cudaStream_t s2;
    cudaStreamCreateWithFlags(&s2, cudaStreamNonBlocking);
    cudaEvent_t evX, evG[4], evF[4];
    cudaEventCreateWithFlags(&evX, cudaEventDisableTiming);
    for (int k = 0; k < 4; k++) {
        cudaEventCreateWithFlags(&evG[k], cudaEventDisableTiming);
        cudaEventCreateWithFlags(&evF[k], cudaEventDisableTiming);
    }

    // ---- prologue ----
    copy_pad_kernel<<<(NP * 32 + TB - 1) / TB, TB>>>(x, xb);                    // main 0
    cudaEventRecord(evX, 0);
    cvt_bf16_kernel<<<(SS * 384 * 32 + TB - 1) / TB, TB>>>(whh, whhb,
                                                           SS * 384 * 32);      // main 1
    zero2_ints<<<(NPS + TB - 1) / TB, TB, 0, s2>>>(ecntp, ecurp, NPS);          // s2
    // main idx 3 (PROFILED): gh GEMM for superstep (0,0)
    {
        GemmArgs ga;
        for (int s = 0; s < 3; s++) {
            ga.A[s] = xb;
            ga.B[s] = whhb + (size_t)s * 384 * 128;
            ga.bias[s] = bhh + s * 384;
            ga.C[s] = gh3 + (size_t)s * NP * 384;
        }
        bf16_gemm<<<g3, GEMM_T, BG_SMEM>>>(ga, 384, M_TILES);
    }
    // s2: CSR + first gather
    ecount_kernel<<<(EE + TB - 1) / TB, TB, 0, s2>>>(dst, eattr, ecntp, EE);
    scan_kernel<<<1, 1024, 0, s2>>>(ecntp, eoffp, NPS);
    fill_kernel<<<(EE + TB - 1) / TB, TB, 0, s2>>>(src, dst, eattr, eoffp, ecurp, bsrcp, EE);
    cudaStreamWaitEvent(s2, evX, 0);
    {
        Feat3 f; f.p[0] = xb; f.p[1] = xb; f.p[2] = xb;
        gather3_kernel<<<(SS * NP * 32 + TB - 1) / TB, TB, 0, s2>>>(eoffp, bsrcp, f, agg3);
    }
    cudaEventRecord(evG[0], s2);
    // main: weight prep (block-interleaved)
    cvt_wih_il_kernel<<<(SS * 384 * 32 + TB - 1) / TB, TB>>>(wih, wihb);
    cvt_bf16_kernel<<<(SS * 2 * 128 * 32 + TB - 1) / TB, TB>>>(W, Wb, SS * 2 * 128 * 32);
    bihr_kernel<<<(SS * 384 + TB - 1) / TB, TB>>>(bih, bihrp);
    {
        GemmArgs ga;
        for (int z = 0; z < 6; z++) {
            int s = z / 2, i = z % 2;
            ga.A[z] = wihb + (size_t)s * 384 * 128;
            ga.B[z] = Wb + (size_t)(s * 2 + i) * 128 * 128;
            ga.bias[z] = nullptr;
            ga.C[z] = (i == 0 ? wcb : wcb2) + (size_t)s * 384 * 128;
        }
        bf16_gemm<<<dim3(1, 3, 6), GEMM_T, BG_SMEM>>>(ga, 128, 3);
    }

    // ---- main loop: 4 supersteps ----
    int step = 0;
    for (int pass = 0; pass < 2; pass++) {
        for (int i = 0; i < 2; i++, step++) {
            if (step > 0) {
                cudaEventRecord(evF[step], 0);
                cudaStreamWaitEvent(s2, evF[step], 0);
                Feat3 f;
                if (i == 0) { f.p[0] = xb; f.p[1] = xb; f.p[2] = xb; }
                else {
                    f.p[0] = hb3;
                    f.p[1] = hb3 + (size_t)NP * 128;
                    f.p[2] = hb3 + (size_t)2 * NP * 128;
                }
                gather3_kernel<<<(SS * NP * 32 + TB - 1) / TB, TB, 0, s2>>>(
                    eoffp, bsrcp, f, agg3);
                cudaEventRecord(evG[step], s2);
                GemmArgs ga;
                for (int s = 0; s < 3; s++) {
                    ga.A[s] = (i == 0) ? xb : (hb3 + (size_t)s * NP * 128);
                    ga.B[s] = whhb + (size_t)s * 384 * 128;
                    ga.bias[s] = bhh + s * 384;
                    ga.C[s] = gh3 + (size_t)s * NP * 384;
                }
                bf16_gemm<<<g3, GEMM_T, BG_SMEM>>>(ga, 384, M_TILES);
            }
            cudaStreamWaitEvent(0, evG[step], 0);
            {
                FusedArgs fa;
                for (int s = 0; s < 3; s++) {
                    fa.A[s] = agg3 + (size_t)s * NP * 128;
                    fa.B[s] = (i == 0 ? wcb : wcb2) + (size_t)s * 384 * 128;
                    fa.gh[s] = gh3 + (size_t)s * NP * 384;
                    fa.hold[s] = (i == 0) ? xb : (hb3 + (size_t)s * NP * 128);
                    fa.out[s] = hb3 + (size_t)s * NP * 128;
                    fa.bias[s] = bihrp + s * 384;
                }
                gemm_gru<<<fg, GEMM_T, FG_SMEM>>>(fa, M_TILES);
            }
            if (i == 1)
                avg3_kernel<<<(NP * 32 + TB - 1) / TB, TB>>>(hb3, xb);
        }
    }

    // ---- pooling + MLP ----
    zero_kernel<<<(GG * DD / 4 + TB - 1) / TB, TB>>>(poolp, GG * DD / 4);
    zero_kernel<<<1, GG / 4>>>(cntp, GG / 4);
    cnt_kernel<<<(NN + TB - 1) / TB, TB>>>(batch, cntp, NN);
    pool_kernel<<<(NN * 32 + TB - 1) / TB, TB>>>(xb, batch, poolp);
    mlp_kernel<<<1, 256>>>(poolp, cntp, pt, fc1w, fc1b, fc2w, fc2b, fclw, fclb, out);

    cudaStreamCaptureStatus cap = cudaStreamCaptureStatusNone;
    cudaStreamIsCapturing(0, &cap);
    if (cap == cudaStreamCaptureStatusNone) {
        cudaEventDestroy(evX);
        for (int k = 0; k < 4; k++) { cudaEventDestroy(evG[k]); cudaEventDestroy(evF[k]); }
        cudaStreamDestroy(s2);
    }
}

// round 17
// speedup vs baseline: 1.1321x; 1.0466x over previous
#include <cuda_runtime.h>
#include <cuda_bf16.h>
#include <math.h>
#include <stdint.h>

#define NN 100000
#define NP 100096
#define EE 600000
#define DD 128
#define SS 3
#define GG 64
#define OUTD 2
#define NPS (SS * NP)
#define M_TILES (NP / 128)        // 782

// ---------------- device scratch ----------------
__device__ __nv_bfloat16 g_xb[NP * DD];
__device__ __nv_bfloat16 g_hb3[SS * NP * DD];
__device__ __nv_bfloat16 g_agg3[SS * NP * DD];
__device__ __nv_bfloat16 g_gh3[SS * NP * 3 * DD];
__device__ __nv_bfloat16 g_wcb[SS * 3 * DD * DD];
__device__ __nv_bfloat16 g_wcb2[SS * 3 * DD * DD];
__device__ __nv_bfloat16 g_wihb[SS * 3 * DD * DD];
__device__ __nv_bfloat16 g_whhb[SS * 3 * DD * DD];
__device__ __nv_bfloat16 g_Wb[SS * 2 * DD * DD];
__device__ float g_bihr[SS * 3 * DD];
__device__ float g_pool[GG * DD];
__device__ float g_cnt[GG];
__device__ int   g_bsrc[EE];
__device__ int   g_ecnt[NPS];
__device__ int   g_ecur[NPS];
__device__ int   g_eoff[NPS + 1];

// ---------------- tiny utils ----------------
__global__ void zero_kernel(float* __restrict__ p, int n4) {
    int i = blockIdx.x * blockDim.x + threadIdx.x;
    if (i < n4) ((float4*)p)[i] = make_float4(0.f, 0.f, 0.f, 0.f);
}
__global__ void copy_pad_kernel(const float* __restrict__ x, __nv_bfloat16* __restrict__ xb) {
    int i = blockIdx.x * blockDim.x + threadIdx.x;
    if (i >= NP * 32) return;
    int n = i >> 5;
    float4 v = make_float4(0.f, 0.f, 0.f, 0.f);
    if (n < NN) v = ((const float4*)x)[i];
    *(__nv_bfloat162*)(xb + (size_t)i * 4)     = __floats2bfloat162_rn(v.x, v.y);
    *(__nv_bfloat162*)(xb + (size_t)i * 4 + 2) = __floats2bfloat162_rn(v.z, v.w);
}
__global__ void cvt_bf16_kernel(const float* __restrict__ src,
                                __nv_bfloat16* __restrict__ dst, int n4) {
    int i = blockIdx.x * blockDim.x + threadIdx.x;
    if (i >= n4) return;
    float4 v = ((const float4*)src)[i];
    *(__nv_bfloat162*)(dst + (size_t)i * 4)     = __floats2bfloat162_rn(v.x, v.y);
    *(__nv_bfloat162*)(dst + (size_t)i * 4 + 2) = __floats2bfloat162_rn(v.z, v.w);
}
// wih rows: j = g*128+d  ->  jil = (d/8)*24 + g*8 + (d%8)
__global__ void cvt_wih_il_kernel(const float* __restrict__ wih,
                                  __nv_bfloat16* __restrict__ dst) {
    int i = blockIdx.x * blockDim.x + threadIdx.x;
    if (i >= SS * 384 * 32) return;
    int s = i / (384 * 32);
    int rem = i - s * 384 * 32;
    int j = rem >> 5;
    int k4 = (rem & 31) * 4;
    int g = j >> 7;
    int d = j & 127;
    int jil = (d >> 3) * 24 + g * 8 + (d & 7);
    float4 v = *(const float4*)(wih + (size_t)(s * 384 + j) * 128 + k4);
    __nv_bfloat16* o = dst + (size_t)(s * 384 + jil) * 128 + k4;
    *(__nv_bfloat162*)(o)     = __floats2bfloat162_rn(v.x, v.y);
    *(__nv_bfloat162*)(o + 2) = __floats2bfloat162_rn(v.z, v.w);
}
__global__ void bihr_kernel(const float* __restrict__ bih, float* __restrict__ bihr) {
    int i = blockIdx.x * blockDim.x + threadIdx.x;
    if (i >= SS * 384) return;
    int s = i / 384;
    int j = i - s * 384;
    int g = j >> 7;
    int d = j & 127;
    int jil = (d >> 3) * 24 + g * 8 + (d & 7);
    bihr[s * 384 + jil] = bih[i];
}
__global__ void zero2_ints(int* __restrict__ a, int* __restrict__ b, int n) {
    int i = blockIdx.x * blockDim.x + threadIdx.x;
    if (i < n) { a[i] = 0; b[i] = 0; }
}

// ---------------- CSR build ----------------
__global__ void ecount_kernel(const int* __restrict__ dst, const int* __restrict__ attr,
                              int* __restrict__ cnt, int E) {
    int e = blockIdx.x * blockDim.x + threadIdx.x;
    if (e < E) atomicAdd(&cnt[attr[e] * NP + dst[e]], 1);
}
__global__ void scan_kernel(const int* __restrict__ cnt, int* __restrict__ off, int n) {
    __shared__ int ssum[1024];
    int t = threadIdx.x;
    int per = (n + 1023) / 1024;
    int b0 = t * per;
    int b1 = b0 + per; if (b1 > n) b1 = n; if (b0 > n) b0 = n;
    int s = 0;
    for (int i = b0; i < b1; i++) s += cnt[i];
    ssum[t] = s;
    __syncthreads();
    for (int d = 1; d < 1024; d <<= 1) {
        int v = (t >= d) ? ssum[t - d] : 0;
        __syncthreads();
        ssum[t] += v;
        __syncthreads();
    }
    int run = (t == 0) ? 0 : ssum[t - 1];
    if (t == 1023) off[n] = ssum[1023];
    for (int i = b0; i < b1; i++) { off[i] = run; run += cnt[i]; }
}
__global__ void fill_kernel(const int* __restrict__ src, const int* __restrict__ dst,
                            const int* __restrict__ attr, const int* __restrict__ off,
                            int* __restrict__ cur, int* __restrict__ bsrc, int E) {
    int e = blockIdx.x * blockDim.x + threadIdx.x;
    if (e >= E) return;
    int idx = attr[e] * NP + dst[e];
    int pos = off[idx] + atomicAdd(&cur[idx], 1);
    bsrc[pos] = src[e];
}

// ---------------- gather all 3 types ----------------
struct Feat3 { const __nv_bfloat16* p[3]; };

__global__ void gather3_kernel(const int* __restrict__ off, const int* __restrict__ bsrc,
                               Feat3 f, __nv_bfloat16* __restrict__ agg3) {
    int w = (blockIdx.x * blockDim.x + threadIdx.x) >> 5;
    int lane = threadIdx.x & 31;
    if (w >= SS * NP) return;
    int s = w / NP;
    const __nv_bfloat16* feat = f.p[s];
    int e0 = off[w], e1 = off[w + 1];
    float a0 = 0.f, a1 = 0.f, a2 = 0.f, a3 = 0.f;
    for (int e = e0; e < e1; e++) {
        int sn = bsrc[e];
        uint2 u = *(const uint2*)(feat + (size_t)sn * DD + lane * 4);
        __nv_bfloat162 p0 = *(__nv_bfloat162*)&u.x;
        __nv_bfloat162 p1 = *(__nv_bfloat162*)&u.y;
        float2 f0 = __bfloat1622float2(p0), f1 = __bfloat1622float2(p1);
        a0 += f0.x; a1 += f0.y; a2 += f1.x; a3 += f1.y;
    }
    if (e1 > e0) {
        float inv = 1.0f / (float)(e1 - e0);
        a0 *= inv; a1 *= inv; a2 *= inv; a3 *= inv;
    }
    uint2 o;
    *(__nv_bfloat162*)&o.x = __floats2bfloat162_rn(a0, a1);
    *(__nv_bfloat162*)&o.y = __floats2bfloat162_rn(a2, a3);
    *(uint2*)(agg3 + (size_t)w * DD + lane * 4) = o;
}

// ---------------- mma helpers ----------------
#define LDTB 136
__device__ __forceinline__ void cp16(void* s, const void* g) {
    uint32_t sa = (uint32_t)__cvta_generic_to_shared(s);
    asm volatile("cp.async.cg.shared.global [%0], [%1], 16;" :: "r"(sa), "l"(g));
}
__device__ __forceinline__ void ldm_x4(uint32_t* r, const __nv_bfloat16* p) {
    uint32_t sa = (uint32_t)__cvta_generic_to_shared(p);
    asm volatile("ldmatrix.sync.aligned.m8n8.x4.shared.b16 {%0,%1,%2,%3}, [%4];"
                 : "=r"(r[0]), "=r"(r[1]), "=r"(r[2]), "=r"(r[3]) : "r"(sa));
}
__device__ __forceinline__ void ldm_x2(uint32_t* r, const __nv_bfloat16* p) {
    uint32_t sa = (uint32_t)__cvta_generic_to_shared(p);
    asm volatile("ldmatrix.sync.aligned.m8n8.x2.shared.b16 {%0,%1}, [%2];"
                 : "=r"(r[0]), "=r"(r[1]) : "r"(sa));
}
__device__ __forceinline__ void mma16816(float* c, const uint32_t* a, const uint32_t* b) {
    asm volatile(
        "mma.sync.aligned.m16n8k16.row.col.f32.bf16.bf16.f32 "
        "{%0,%1,%2,%3}, {%4,%5,%6,%7}, {%8,%9}, {%0,%1,%2,%3};"
        : "+f"(c[0]), "+f"(c[1]), "+f"(c[2]), "+f"(c[3])
        : "r"(a[0]), "r"(a[1]), "r"(a[2]), "r"(a[3]), "r"(b[0]), "r"(b[1]));
}
__device__ __forceinline__ float tanhapx(float x) {
    float y;
    asm("tanh.approx.f32 %0, %1;" : "=f"(y) : "f"(x));
    return y;
}
__device__ __forceinline__ float sigf(float x) {
    return 0.5f * tanhapx(0.5f * x) + 0.5f;
}
__device__ __forceinline__ float4 ldbf4(const __nv_bfloat16* p) {
    uint2 u = *(const uint2*)p;
    __nv_bfloat162 a = *(__nv_bfloat162*)&u.x;
    __nv_bfloat162 b = *(__nv_bfloat162*)&u.y;
    float2 fa = __bfloat1622float2(a), fb = __bfloat1622float2(b);
    return make_float4(fa.x, fa.y, fb.x, fb.y);
}
__device__ __forceinline__ void stbf4(__nv_bfloat16* p, float4 v) {
    uint2 u;
    *(__nv_bfloat162*)&u.x = __floats2bfloat162_rn(v.x, v.y);
    *(__nv_bfloat162*)&u.y = __floats2bfloat162_rn(v.z, v.w);
    *(uint2*)p = u;
}

// ========== plain weights-stationary GEMM (gh + wc), R12 core ==========
#define SMB_B (128 * LDTB * 2)
#define SMB_A (128 * LDTB * 2)
#define BG_SMEM (SMB_B + 2 * SMB_A)  // 104448
#define GEMM_T 512

struct GemmArgs {
    const __nv_bfloat16* A[6];
    const __nv_bfloat16* B[6];
    const float* bias[6];
    __nv_bfloat16* C[6];
};

__global__ void __launch_bounds__(GEMM_T, 1)
bf16_gemm(GemmArgs ga, int J, int mtiles) {
    int z = blockIdx.z;
    const __nv_bfloat16* A = ga.A[z];
    const __nv_bfloat16* B = ga.B[z];
    const float* bias = ga.bias[z];
    __nv_bfloat16* C = ga.C[z];

    extern __shared__ char smx[];
    __nv_bfloat16* Bs = (__nv_bfloat16*)smx;
    __nv_bfloat16* Abuf0 = (__nv_bfloat16*)(smx + SMB_B);
    __nv_bfloat16* Abuf1 = (__nv_bfloat16*)(smx + SMB_B + SMB_A);

    int tid = threadIdx.x;
    int warp = tid >> 5;
    int lane = tid & 31;
    int mb = (warp >> 2) * 32;
    int nb = (warp & 3) * 32;
    int bn = blockIdx.x * 128;

    int mt = blockIdx.y;
    if (mt >= mtiles) return;

    for (int slot = tid; slot < 128 * 16; slot += GEMM_T) {
        int r = slot >> 4;
        int c8 = (slot & 15) * 8;
        cp16(Bs + r * LDTB + c8, B + (size_t)(bn + r) * 128 + c8);
    }
    asm volatile("cp.async.commit_group;");
    for (int slot = tid; slot < 128 * 16; slot += GEMM_T) {
        int r = slot >> 4;
        int c8 = (slot & 15) * 8;
        cp16(Abuf0 + r * LDTB + c8, A + (size_t)mt * 128 * 128 + (size_t)r * 128 + c8);
    }
    asm volatile("cp.async.commit_group;");
    asm volatile("cp.async.wait_group 1;");
    __syncthreads();

    uint32_t bf[4][8][2];
    {
        int lr = lane & 7;
        int ls = (lane >> 3) & 1;
#pragma unroll
        for (int nt = 0; nt < 4; nt++)
#pragma unroll
            for (int kt = 0; kt < 8; kt++)
                ldm_x2(bf[nt][kt], Bs + (nb + nt * 8 + lr) * LDTB + kt * 16 + ls * 8);
    }

    int buf = 0;
    while (mt < mtiles) {
        int nxt = mt + gridDim.y;
        bool pf = (nxt < mtiles);
        __nv_bfloat16* Acur = buf ? Abuf1 : Abuf0;
        __nv_bfloat16* Aalt = buf ? Abuf0 : Abuf1;
        if (pf) {
            for (int slot = tid; slot < 128 * 16; slot += GEMM_T) {
                int r = slot >> 4;
                int c8 = (slot & 15) * 8;
                cp16(Aalt + r * LDTB + c8,
                     A + (size_t)nxt * 128 * 128 + (size_t)r * 128 + c8);
            }
            asm volatile("cp.async.commit_group;");
            asm volatile("cp.async.wait_group 1;");
        } else {
            asm volatile("cp.async.wait_group 0;");
        }
        __syncthreads();

        float acc[2][4][4];
#pragma unroll
        for (int i = 0; i < 2; i++)
#pragma unroll
            for (int nt = 0; nt < 4; nt++)
#pragma unroll
                for (int e = 0; e < 4; e++) acc[i][nt][e] = 0.f;

        int q = lane >> 3;
        int arow = (q & 1) * 8 + (lane & 7);
        int acol = (q >> 1) * 8;
#pragma unroll
        for (int kt = 0; kt < 8; kt++) {
            uint32_t a[2][4];
#pragma unroll
            for (int i = 0; i < 2; i++)
                ldm_x4(a[i], Acur + (mb + i * 16 + arow) * LDTB + kt * 16 + acol);
#pragma unroll
            for (int i = 0; i < 2; i++)
#pragma unroll
                for (int nt = 0; nt < 4; nt++)
                    mma16816(acc[i][nt], a[i], bf[nt][kt]);
        }

        int bm = mt * 128;
#pragma unroll
        for (int i = 0; i < 2; i++) {
#pragma unroll
            for (int nt = 0; nt < 4; nt++) {
                int r0 = bm + mb + i * 16 + (lane >> 2);
                int cc = bn + nb + nt * 8 + ((lane & 3) << 1);
                float b0v = 0.f, b1v = 0.f;
                if (bias != nullptr) { b0v = bias[cc]; b1v = bias[cc + 1]; }
                *(__nv_bfloat162*)(C + (size_t)r0 * J + cc) =
                    __floats2bfloat162_rn(acc[i][nt][0] + b0v, acc[i][nt][1] + b1v);
                *(__nv_bfloat162*)(C + (size_t)(r0 + 8) * J + cc) =
                    __floats2bfloat162_rn(acc[i][nt][2] + b0v, acc[i][nt][3] + b1v);
            }
        }
        __syncthreads();
        mt = nxt;
        buf ^= 1;
    }
}

// ========== fused gi-GEMM + GRU with fully-pipelined gh/hold prefetch ==========
// Stripe = 96 cols (4 dim-blocks x 3 gates x 8). Warp tile 32x24.
// A, gh-slice and hold-slice all cp.async double-buffered; GRU phase is pure LDS.
#define SMB_B2 (96 * LDTB * 2)           // 26112
#define GH_LD 104
#define GH_S (128 * GH_LD * 2)           // 26624
#define HD_LD 40
#define HD_S (128 * HD_LD * 2)           // 10240
#define FG_SMEM (SMB_B2 + 2 * SMB_A + 2 * GH_S + 2 * HD_S)   // 169472
#define STRC 104

struct FusedArgs {
    const __nv_bfloat16* A[3];
    const __nv_bfloat16* B[3];
    const __nv_bfloat16* gh[3];
    const __nv_bfloat16* hold[3];
    __nv_bfloat16* out[3];
    const float* bias[3];
};

__global__ void __launch_bounds__(GEMM_T, 1)
gemm_gru(FusedArgs fa, int mtiles) {
    int s = blockIdx.z;
    const __nv_bfloat16* A = fa.A[s];
    const __nv_bfloat16* B = fa.B[s];
    const __nv_bfloat16* gh = fa.gh[s];
    const __nv_bfloat16* hold = fa.hold[s];
    __nv_bfloat16* outp = fa.out[s];
    const float* bias = fa.bias[s];

    extern __shared__ char smx[];
    __nv_bfloat16* Bs = (__nv_bfloat16*)smx;
    __nv_bfloat16* Abuf[2] = { (__nv_bfloat16*)(smx + SMB_B2),
                               (__nv_bfloat16*)(smx + SMB_B2 + SMB_A) };
    __nv_bfloat16* Ghb[2] = { (__nv_bfloat16*)(smx + SMB_B2 + 2 * SMB_A),
                              (__nv_bfloat16*)(smx + SMB_B2 + 2 * SMB_A + GH_S) };
    __nv_bfloat16* Hdb[2] = { (__nv_bfloat16*)(smx + SMB_B2 + 2 * SMB_A + 2 * GH_S),
                              (__nv_bfloat16*)(smx + SMB_B2 + 2 * SMB_A + 2 * GH_S + HD_S) };

    int tid = threadIdx.x;
    int warp = tid >> 5;
    int lane = tid & 31;
    int mb = (warp >> 2) * 32;
    int nb = (warp & 3) * 24;
    int bnr = blockIdx.x * 96;
    int D0 = blockIdx.x * 32;

    int mt = blockIdx.y;
    if (mt >= mtiles) return;

    // B stripe
    for (int slot = tid; slot < 96 * 16; slot += GEMM_T) {
        int r = slot >> 4;
        int c8 = (slot & 15) * 8;
        cp16(Bs + r * LDTB + c8, B + (size_t)(bnr + r) * 128 + c8);
    }
    asm volatile("cp.async.commit_group;");
    // tile 0: A + gh slice + hold slice
    {
        size_t bm0 = (size_t)mt * 128;
        for (int slot = tid; slot < 128 * 16; slot += GEMM_T) {
            int r = slot >> 4;
            int c8 = (slot & 15) * 8;
            cp16(Abuf[0] + r * LDTB + c8, A + (bm0 + r) * 128 + c8);
        }
        for (int slot = tid; slot < 128 * 12; slot += GEMM_T) {
            int r = slot / 12;
            int c = slot - r * 12;
            int g = c >> 2;
            int k8 = (c & 3) * 8;
            cp16(Ghb[0] + r * GH_LD + g * 32 + k8,
                 gh + (bm0 + r) * 384 + g * 128 + D0 + k8);
        }
        for (int slot = tid; slot < 128 * 4; slot += GEMM_T) {
            int r = slot >> 2;
            int k8 = (slot & 3) * 8;
            cp16(Hdb[0] + r * HD_LD + k8, hold + (bm0 + r) * 128 + D0 + k8);
        }
    }
    asm volatile("cp.async.commit_group;");
    asm volatile("cp.async.wait_group 1;");
    __syncthreads();

    uint32_t bfr[3][8][2];
    {
        int lr = lane & 7;
        int ls = (lane >> 3) & 1;
#pragma unroll
        for (int nt = 0; nt < 3; nt++)
#pragma unroll
            for (int kt = 0; kt < 8; kt++)
                ldm_x2(bfr[nt][kt], Bs + (nb + nt * 8 + lr) * LDTB + kt * 16 + ls * 8);
    }

    float bg0[3], bg1[3];
#pragma unroll
    for (int g = 0; g < 3; g++) {
        bg0[g] = bias[bnr + nb + g * 8 + ((lane & 3) << 1)];
        bg1[g] = bias[bnr + nb + g * 8 + ((lane & 3) << 1) + 1];
    }
    int dcol = (warp & 3) * 8 + ((lane & 3) << 1);

    int buf = 0;
    while (mt < mtiles) {
        int nxt = mt + gridDim.y;
        bool pf = (nxt < mtiles);
        __nv_bfloat16* Acur = Abuf[buf];
        __nv_bfloat16* Ghc = Ghb[buf];
        __nv_bfloat16* Hdc = Hdb[buf];
        if (pf) {
            size_t bmn = (size_t)nxt * 128;
            __nv_bfloat16* Aalt = Abuf[buf ^ 1];
            __nv_bfloat16* Gha = Ghb[buf ^ 1];
            __nv_bfloat16* Hda = Hdb[buf ^ 1];
            for (int slot = tid; slot < 128 * 16; slot += GEMM_T) {
                int r = slot >> 4;
                int c8 = (slot & 15) * 8;
                cp16(Aalt + r * LDTB + c8, A + (bmn + r) * 128 + c8);
            }
            for (int slot = tid; slot < 128 * 12; slot += GEMM_T) {
                int r = slot / 12;
                int c = slot - r * 12;
                int g = c >> 2;
                int k8 = (c & 3) * 8;
                cp16(Gha + r * GH_LD + g * 32 + k8,
                     gh + (bmn + r) * 384 + g * 128 + D0 + k8);
            }
            for (int slot = tid; slot < 128 * 4; slot += GEMM_T) {
                int r = slot >> 2;
                int k8 = (slot & 3) * 8;
                cp16(Hda + r * HD_LD + k8, hold + (bmn + r) * 128 + D0 + k8);
            }
            asm volatile("cp.async.commit_group;");
            asm volatile("cp.async.wait_group 1;");
        } else {
            asm volatile("cp.async.wait_group 0;");
        }
        __syncthreads();

        float acc[2][3][4];
#pragma unroll
        for (int i = 0; i < 2; i++)
#pragma unroll
            for (int nt = 0; nt < 3; nt++)
#pragma unroll
                for (int e = 0; e < 4; e++) acc[i][nt][e] = 0.f;

        int q = lane >> 3;
        int arow = (q & 1) * 8 + (lane & 7);
        int acol = (q >> 1) * 8;
#pragma unroll
        for (int kt = 0; kt < 8; kt++) {
            uint32_t a[2][4];
#pragma unroll
            for (int i = 0; i < 2; i++)
                ldm_x4(a[i], Acur + (mb + i * 16 + arow) * LDTB + kt * 16 + acol);
#pragma unroll
            for (int i = 0; i < 2; i++)
#pragma unroll
                for (int nt = 0; nt < 3; nt++)
                    mma16816(acc[i][nt], a[i], bfr[nt][kt]);
        }
        __syncthreads();

        // stage gi (+bias) de-interleaved into Acur: Cs[row][gate*32+dim]
        __nv_bfloat16* Cs = Acur;
#pragma unroll
        for (int i = 0; i < 2; i++) {
#pragma unroll
            for (int nt = 0; nt < 3; nt++) {
                int r0 = mb + i * 16 + (lane >> 2);
                int cc = nt * 32 + dcol;
                *(__nv_bfloat162*)(Cs + r0 * STRC + cc) =
                    __floats2bfloat162_rn(acc[i][nt][0] + bg0[nt], acc[i][nt][1] + bg1[nt]);
                *(__nv_bfloat162*)(Cs + (r0 + 8) * STRC + cc) =
                    __floats2bfloat162_rn(acc[i][nt][2] + bg0[nt], acc[i][nt][3] + bg1[nt]);
            }
        }
        __syncthreads();

        // GRU: everything from smem; only the output store touches gmem
        int bm = mt * 128;
#pragma unroll
        for (int it = 0; it < 2; it++) {
            int g = tid + it * GEMM_T;
            int row = g >> 3;
            int d4 = (g & 7) << 2;
            const __nv_bfloat16* crow = Cs + row * STRC;
            float4 ir  = ldbf4(crow + d4);
            float4 iz  = ldbf4(crow + 32 + d4);
            float4 in4 = ldbf4(crow + 64 + d4);
            const __nv_bfloat16* ghr = Ghc + row * GH_LD;
            float4 hr = ldbf4(ghr + d4);
            float4 hz = ldbf4(ghr + 32 + d4);
            float4 hn = ldbf4(ghr + 64 + d4);
            float4 h = ldbf4(Hdc + row * HD_LD + d4);
            float4 o;
            { float r = sigf(ir.x + hr.x), z = sigf(iz.x + hz.x);
              float nn = tanhapx(in4.x + r * hn.x); o.x = (1.f - z) * nn + z * h.x; }
            { float r = sigf(ir.y + hr.y), z = sigf(iz.y + hz.y);
              float nn = tanhapx(in4.y + r * hn.y); o.y = (1.f - z) * nn + z * h.y; }
            { float r = sigf(ir.z + hr.z), z = sigf(iz.z + hz.z);
              float nn = tanhapx(in4.z + r * hn.z); o.z = (1.f - z) * nn + z * h.z; }
            { float r = sigf(ir.w + hr.w), z = sigf(iz.w + hz.w);
              float nn = tanhapx(in4.w + r * hn.w); o.w = (1.f - z) * nn + z * h.w; }
            stbf4(outp + (size_t)(bm + row) * 128 + D0 + d4, o);
        }
        __syncthreads();
        mt = nxt;
        buf ^= 1;
    }
}

// xb = mean over s of hb3[s]
__global__ void avg3_kernel(const __nv_bfloat16* __restrict__ hb3,
                            __nv_bfloat16* __restrict__ xb) {
    int i = blockIdx.x * blockDim.x + threadIdx.x;
    if (i >= NP * 32) return;
    size_t p = (size_t)i * 4;
    float4 a = ldbf4(hb3 + p);
    float4 b = ldbf4(hb3 + (size_t)NP * 128 + p);
    float4 c = ldbf4(hb3 + (size_t)2 * NP * 128 + p);
    float4 v;
    v.x = (a.x + b.x + c.x) * (1.0f / 3.0f);
    v.y = (a.y + b.y + c.y) * (1.0f / 3.0f);
    v.z = (a.z + b.z + c.z) * (1.0f / 3.0f);
    v.w = (a.w + b.w + c.w) * (1.0f / 3.0f);
    stbf4(xb + p, v);
}

// ---------------- pooling / MLP ----------------
__global__ void cnt_kernel(const int* __restrict__ batch, float* __restrict__ cnt, int n) {
    int i = blockIdx.x * blockDim.x + threadIdx.x;
    if (i < n) atomicAdd(&cnt[batch[i]], 1.0f);
}
__global__ void pool_kernel(const __nv_bfloat16* __restrict__ xb, const int* __restrict__ batch,
                            float* __restrict__ pool) {
    int idx = blockIdx.x * blockDim.x + threadIdx.x;
    if (idx >= NN * 32) return;
    int n = idx >> 5;
    int c = (idx & 31) * 4;
    int g = batch[n];
    float4 v = ldbf4(xb + (size_t)n * 128 + c);
    float* o = pool + (size_t)g * 128 + c;
    asm volatile("red.global.add.v4.f32 [%0], {%1,%2,%3,%4};"
                 :: "l"(o), "f"(v.x), "f"(v.y), "f"(v.z), "f"(v.w) : "memory");
}
__global__ void mlp_kernel(const float* __restrict__ pool, const float* __restrict__ cnt,
                           const float* __restrict__ pt,
                           const float* __restrict__ fc1w, const float* __restrict__ fc1b,
                           const float* __restrict__ fc2w, const float* __restrict__ fc2b,
                           const float* __restrict__ fclw, const float* __restrict__ fclb,
                           float* __restrict__ out) {
    __shared__ float h1[GG * 80];
    __shared__ float h2[GG * 80];
    int tid = threadIdx.x;
    for (int t = tid; t < GG * 80; t += blockDim.x) {
        int g = t / 80, j = t - (t / 80) * 80;
        float ic = 1.0f / fmaxf(cnt[g], 1.0f);
        float acc = fc1b[j];
        const float* w = fc1w + j * 129;
        const float* p = pool + g * 128;
        for (int k = 0; k < 128; k++) acc = fmaf(p[k] * ic, w[k], acc);
        acc = fmaf(pt[g], w[128], acc);
        h1[t] = acc > 0.f ? acc : 0.01f * acc;
    }
    __syncthreads();
    for (int t = tid; t < GG * 80; t += blockDim.x) {
        int g = t / 80, j = t - (t / 80) * 80;
        float acc = fc2b[j];
        const float* w = fc2w + j * 80;
        const float* hh = h1 + g * 80;
        for (int k = 0; k < 80; k++) acc = fmaf(hh[k], w[k], acc);
        h2[t] = acc > 0.f ? acc : 0.01f * acc;
    }
    __syncthreads();
    for (int t = tid; t < GG * OUTD; t += blockDim.x) {
        int g = t / OUTD, o = t - (t / OUTD) * OUTD;
        float acc = fclb[o];
        const float* w = fclw + o * 80;
        const float* hh = h2 + g * 80;
        for (int k = 0; k < 80; k++) acc = fmaf(hh[k], w[k], acc);
        out[t] = acc;
    }
}

// ---------------- host launcher ----------------
extern "C" void kernel_launch(void* const* d_in, const int* in_sizes, int n_in,
                              void* d_out, int out_size) {
    (void)in_sizes; (void)n_in; (void)out_size;
    const float* x     = (const float*)d_in[0];
    const int*   eidx  = (const int*)d_in[1];
    const int*   eattr = (const int*)d_in[2];
    const int*   batch = (const int*)d_in[3];
    const float* pt    = (const float*)d_in[4];
    const float* W     = (const float*)d_in[5];
    const float* wih   = (const float*)d_in[6];
    const float* whh   = (const float*)d_in[7];
    const float* bih   = (const float*)d_in[8];
    const float* bhh   = (const float*)d_in[9];
    const float* fc1w  = (const float*)d_in[10];
    const float* fc1b  = (const float*)d_in[11];
    const float* fc2w  = (const float*)d_in[12];
    const float* fc2b  = (const float*)d_in[13];
    const float* fclw  = (const float*)d_in[14];
    const float* fclb  = (const float*)d_in[15];
    float* out = (float*)d_out;

    const int* src = eidx;
    const int* dst = eidx + EE;

    float *poolp, *cntp, *bihrp;
    __nv_bfloat16 *xb, *hb3, *agg3, *gh3, *wcb, *wcb2, *wihb, *whhb, *Wb;
    int *bsrcp, *ecntp, *ecurp, *eoffp;
    cudaGetSymbolAddress((void**)&xb,    g_xb);
    cudaGetSymbolAddress((void**)&hb3,   g_hb3);
    cudaGetSymbolAddress((void**)&agg3,  g_agg3);
    cudaGetSymbolAddress((void**)&gh3,   g_gh3);
    cudaGetSymbolAddress((void**)&wcb,   g_wcb);
    cudaGetSymbolAddress((void**)&wcb2,  g_wcb2);
    cudaGetSymbolAddress((void**)&wihb,  g_wihb);
    cudaGetSymbolAddress((void**)&whhb,  g_whhb);
    cudaGetSymbolAddress((void**)&Wb,    g_Wb);
    cudaGetSymbolAddress((void**)&bihrp, g_bihr);
    cudaGetSymbolAddress((void**)&poolp, g_pool);
    cudaGetSymbolAddress((void**)&cntp,  g_cnt);
    cudaGetSymbolAddress((void**)&bsrcp, g_bsrc);
    cudaGetSymbolAddress((void**)&ecntp, g_ecnt);
    cudaGetSymbolAddress((void**)&ecurp, g_ecur);
    cudaGetSymbolAddress((void**)&eoffp, g_eoff);

    cudaFuncSetAttribute(bf16_gemm, cudaFuncAttributeMaxDynamicSharedMemorySize, BG_SMEM);
    cudaFuncSetAttribute(gemm_gru, cudaFuncAttributeMaxDynamicSharedMemorySize, FG_SMEM);

    const int TB = 256;
    dim3 g3(3, 16, 3);
    dim3 fg(4, 12, 3);

    cudaStream_t s2;
    cudaStreamCreateWithFlags(&s2, cudaStreamNonBlocking);
    cudaEvent_t evX, evG[4], evF[4];
    cudaEventCreateWithFlags(&evX, cudaEventDisableTiming);
    for (int k = 0; k < 4; k++) {
        cudaEventCreateWithFlags(&evG[k], cudaEventDisableTiming);
        cudaEventCreateWithFlags(&evF[k], cudaEventDisableTiming);
    }

    // ---- prologue ----
    copy_pad_kernel<<<(NP * 32 + TB - 1) / TB, TB>>>(x, xb);                    // main 0
    cudaEventRecord(evX, 0);
    cvt_bf16_kernel<<<(SS * 384 * 32 + TB - 1) / TB, TB>>>(whh, whhb,
                                                           SS * 384 * 32);      // main 1
    zero2_ints<<<(NPS + TB - 1) / TB, TB, 0, s2>>>(ecntp, ecurp, NPS);          // s2
    // main idx 3 (PROFILED): gh GEMM for superstep (0,0)
    {
        GemmArgs ga;
        for (int s = 0; s < 3; s++) {
            ga.A[s] = xb;
            ga.B[s] = whhb + (size_t)s * 384 * 128;
            ga.bias[s] = bhh + s * 384;
            ga.C[s] = gh3 + (size_t)s * NP * 384;
        }
        bf16_gemm<<<g3, GEMM_T, BG_SMEM>>>(ga, 384, M_TILES);
    }
    // s2: CSR + first gather
    ecount_kernel<<<(EE + TB - 1) / TB, TB, 0, s2>>>(dst, eattr, ecntp, EE);
    scan_kernel<<<1, 1024, 0, s2>>>(ecntp, eoffp, NPS);
    fill_kernel<<<(EE + TB - 1) / TB, TB, 0, s2>>>(src, dst, eattr, eoffp, ecurp, bsrcp, EE);
    cudaStreamWaitEvent(s2, evX, 0);
    {
        Feat3 f; f.p[0] = xb; f.p[1] = xb; f.p[2] = xb;
        gather3_kernel<<<(SS * NP * 32 + TB - 1) / TB, TB, 0, s2>>>(eoffp, bsrcp, f, agg3);
    }
    cudaEventRecord(evG[0], s2);
    // main: weight prep
    cvt_wih_il_kernel<<<(SS * 384 * 32 + TB - 1) / TB, TB>>>(wih, wihb);
    cvt_bf16_kernel<<<(SS * 2 * 128 * 32 + TB - 1) / TB, TB>>>(W, Wb, SS * 2 * 128 * 32);
    bihr_kernel<<<(SS * 384 + TB - 1) / TB, TB>>>(bih, bihrp);
    {
        GemmArgs ga;
        for (int z = 0; z < 6; z++) {
            int s = z / 2, i = z % 2;
            ga.A[z] = wihb + (size_t)s * 384 * 128;
            ga.B[z] = Wb + (size_t)(s * 2 + i) * 128 * 128;
            ga.bias[z] = nullptr;
            ga.C[z] = (i == 0 ? wcb : wcb2) + (size_t)s * 384 * 128;
        }
        bf16_gemm<<<dim3(1, 3, 6), GEMM_T, BG_SMEM>>>(ga, 128, 3);
    }

    // ---- main loop: 4 supersteps ----
    int step = 0;
    for (int pass = 0; pass < 2; pass++) {
        for (int i = 0; i < 2; i++, step++) {
            if (step > 0) {
                cudaEventRecord(evF[step], 0);
                cudaStreamWaitEvent(s2, evF[step], 0);
                Feat3 f;
                if (i == 0) { f.p[0] = xb; f.p[1] = xb; f.p[2] = xb; }
                else {
                    f.p[0] = hb3;
                    f.p[1] = hb3 + (size_t)NP * 128;
                    f.p[2] = hb3 + (size_t)2 * NP * 128;
                }
                gather3_kernel<<<(SS * NP * 32 + TB - 1) / TB, TB, 0, s2>>>(
                    eoffp, bsrcp, f, agg3);
                cudaEventRecord(evG[step], s2);
                GemmArgs ga;
                for (int s = 0; s < 3; s++) {
                    ga.A[s] = (i == 0) ? xb : (hb3 + (size_t)s * NP * 128);
                    ga.B[s] = whhb + (size_t)s * 384 * 128;
                    ga.bias[s] = bhh + s * 384;
                    ga.C[s] = gh3 + (size_t)s * NP * 384;
                }
                bf16_gemm<<<g3, GEMM_T, BG_SMEM>>>(ga, 384, M_TILES);
            }
            cudaStreamWaitEvent(0, evG[step], 0);
            {
                FusedArgs fa;
                for (int s = 0; s < 3; s++) {
                    fa.A[s] = agg3 + (size_t)s * NP * 128;
                    fa.B[s] = (i == 0 ? wcb : wcb2) + (size_t)s * 384 * 128;
                    fa.gh[s] = gh3 + (size_t)s * NP * 384;
                    fa.hold[s] = (i == 0) ? xb : (hb3 + (size_t)s * NP * 128);
                    fa.out[s] = hb3 + (size_t)s * NP * 128;
                    fa.bias[s] = bihrp + s * 384;
                }
                gemm_gru<<<fg, GEMM_T, FG_SMEM>>>(fa, M_TILES);
            }
            if (i == 1)
                avg3_kernel<<<(NP * 32 + TB - 1) / TB, TB>>>(hb3, xb);
        }
    }

    // ---- pooling + MLP ----
    zero_kernel<<<(GG * DD / 4 + TB - 1) / TB, TB>>>(poolp, GG * DD / 4);
    zero_kernel<<<1, GG / 4>>>(cntp, GG / 4);
    cnt_kernel<<<(NN + TB - 1) / TB, TB>>>(batch, cntp, NN);
    pool_kernel<<<(NN * 32 + TB - 1) / TB, TB>>>(xb, batch, poolp);
    mlp_kernel<<<1, 256>>>(poolp, cntp, pt, fc1w, fc1b, fc2w, fc2b, fclw, fclb, out);

    cudaStreamCaptureStatus cap = cudaStreamCaptureStatusNone;
    cudaStreamIsCapturing(0, &cap);
    if (cap == cudaStreamCaptureStatusNone) {
        cudaEventDestroy(evX);
        for (int k = 0; k < 4; k++) { cudaEventDestroy(evG[k]); cudaEventDestroy(evF[k]); }
        cudaStreamDestroy(s2);
    }
}